// round 14
// baseline (speedup 1.0000x reference)
#include <cuda_runtime.h>
#include <cuda_bf16.h>
#include <cstdint>

#define NN 50000
#define EE 600000
#define PP 100000
#define FD 128

// ---- device scratch ----
__device__ float g_agg[NN * FD];
__device__ float g_h1[NN * FD];
__device__ float g_h2[NN * FD];
__device__ int   g_cnt[NN];          // restored to 0 by fill_kernel each run
__device__ int   g_rowstart[NN + 1];
__device__ int   g_csr[EE];

typedef unsigned long long u64;
typedef unsigned int u32;

// bf16 split helpers
__device__ __forceinline__ void bf16_split(float x, unsigned short& h, unsigned short& l) {
    __nv_bfloat16 bh = __float2bfloat16(x);
    float r = x - __bfloat162float(bh);
    __nv_bfloat16 bl = __float2bfloat16(r);
    h = __bfloat16_as_ushort(bh);
    l = __bfloat16_as_ushort(bl);
}
__device__ __forceinline__ u32 pack16(unsigned short lo, unsigned short hi) {
    return (u32)lo | ((u32)hi << 16);
}

// m16n8k16 bf16 MMA, f32 accum
__device__ __forceinline__ void mma16816(float& c0, float& c1, float& c2, float& c3,
                                         u32 a0, u32 a1, u32 a2, u32 a3,
                                         u32 b0, u32 b1) {
    asm volatile(
        "mma.sync.aligned.m16n8k16.row.col.f32.bf16.bf16.f32 "
        "{%0,%1,%2,%3}, {%4,%5,%6,%7}, {%8,%9}, {%0,%1,%2,%3};"
        : "+f"(c0), "+f"(c1), "+f"(c2), "+f"(c3)
        : "r"(a0), "r"(a1), "r"(a2), "r"(a3), "r"(b0), "r"(b1));
}

// split a float4 into bf16 hi/lo uint2s and store at zh/zl + off
__device__ __forceinline__ void split_store4(u32* zh, u32* zl, u32 off, float4 v) {
    unsigned short h0, l0, h1, l1, h2_, l2_, h3_, l3_;
    bf16_split(v.x, h0, l0); bf16_split(v.y, h1, l1);
    bf16_split(v.z, h2_, l2_); bf16_split(v.w, h3_, l3_);
    *(uint2*)(zh + off) = make_uint2(pack16(h0, h1), pack16(h2_, h3_));
    *(uint2*)(zl + off) = make_uint2(pack16(l0, l1), pack16(l2_, l3_));
}

// ============================================================================
// CSR build (proven)
// ============================================================================
__global__ void count_kernel(const int* __restrict__ dst)
{
    int e = blockIdx.x * blockDim.x + threadIdx.x;
    if (e < EE) atomicAdd(&g_cnt[dst[e]], 1);
}

__global__ void __launch_bounds__(1024, 1) scan_kernel()
{
    __shared__ int wsum[32];
    __shared__ int carry;
    int tid = threadIdx.x, lane = tid & 31, w = tid >> 5;
    if (tid == 0) carry = 0;
    __syncthreads();
    for (int base = 0; base < NN; base += 1024) {
        int i = base + tid;
        int v = (i < NN) ? g_cnt[i] : 0;
        int s = v;
#pragma unroll
        for (int off = 1; off < 32; off <<= 1) {
            int t = __shfl_up_sync(0xffffffffu, s, off);
            if (lane >= off) s += t;
        }
        if (lane == 31) wsum[w] = s;
        __syncthreads();
        if (w == 0) {
            int ws = wsum[lane];
#pragma unroll
            for (int off = 1; off < 32; off <<= 1) {
                int t = __shfl_up_sync(0xffffffffu, ws, off);
                if (lane >= off) ws += t;
            }
            wsum[lane] = ws;
        }
        __syncthreads();
        int prev = (w > 0) ? wsum[w - 1] : 0;
        int incl = carry + prev + s;
        if (i < NN) g_rowstart[i + 1] = incl;
        int chunk_total = wsum[31];
        __syncthreads();
        if (tid == 0) carry += chunk_total;
        __syncthreads();
    }
    if (threadIdx.x == 0) g_rowstart[0] = 0;
}

__global__ void fill_kernel(const int* __restrict__ src,
                            const int* __restrict__ dst)
{
    int e = blockIdx.x * blockDim.x + threadIdx.x;
    if (e >= EE) return;
    int d = dst[e];
    int p = atomicAdd(&g_cnt[d], -1) - 1;
    g_csr[g_rowstart[d] + p] = src[e];
}

// ============================================================================
// Aggregate (proven)
// ============================================================================
__global__ void aggregate_kernel(const float* __restrict__ h)
{
    int gw   = (blockIdx.x * blockDim.x + threadIdx.x) >> 5;
    int lane = threadIdx.x & 31;
    if (gw >= NN) return;
    int beg = g_rowstart[gw], end = g_rowstart[gw + 1];
    const float* hp = h + lane * 4;
    float4 acc = make_float4(0.f, 0.f, 0.f, 0.f);
    int e = beg;
    for (; e + 1 < end; e += 2) {
        int s0 = g_csr[e], s1 = g_csr[e + 1];
        float4 v0 = *(const float4*)(hp + s0 * FD);
        float4 v1 = *(const float4*)(hp + s1 * FD);
        acc.x += v0.x + v1.x; acc.y += v0.y + v1.y;
        acc.z += v0.z + v1.z; acc.w += v0.w + v1.w;
    }
    if (e < end) {
        int s0 = g_csr[e];
        float4 v0 = *(const float4*)(hp + s0 * FD);
        acc.x += v0.x; acc.y += v0.y; acc.z += v0.z; acc.w += v0.w;
    }
    float rd = 1.0f / fmaxf((float)(end - beg), 1.0f);
    acc.x *= rd; acc.y *= rd; acc.z *= rd; acc.w *= rd;
    *(float4*)(g_agg + gw * FD + lane * 4) = acc;
}

// ============================================================================
// Half-K SAGE linear via mma.sync, DOUBLE-BUFFERED staging.
// Tile: 64 rows x 128 cols, K=128. 16 warps = 4 rg x 4 cg.
// ============================================================================
#define SPW 136
#define SPZ 68
#define OFF_SWH  0
#define OFF_SWL  (OFF_SWH + 64 * SPW)
#define OFF_SZH0 (OFF_SWL + 64 * SPW)
#define OFF_SZL0 (OFF_SZH0 + 64 * SPZ)
#define OFF_SZH1 (OFF_SZL0 + 64 * SPZ)
#define OFF_SZL1 (OFF_SZH1 + 64 * SPZ)
#define OFF_SB   (OFF_SZL1 + 64 * SPZ)
#define SAGE_U32 (OFF_SB + 128)

template <bool ADD, bool RELU>
__global__ void __launch_bounds__(512, 1)
sage_half_mma(const float* __restrict__ src,
              const float* __restrict__ W,
              const float* __restrict__ b,
              float* __restrict__ out,
              int rpb)
{
    extern __shared__ u32 smu[];
    u32* Wh  = smu + OFF_SWH;
    u32* Wl  = smu + OFF_SWL;
    u32* zhB[2] = { smu + OFF_SZH0, smu + OFF_SZH1 };
    u32* zlB[2] = { smu + OFF_SZL0, smu + OFF_SZL1 };
    float* bs = (float*)(smu + OFF_SB);

    int tid  = threadIdx.x;
    int lane = tid & 31;
    int warp = tid >> 5;
    int g    = lane >> 2;
    int tg   = lane & 3;
    int wr   = warp & 3;
    int wc   = warp >> 2;

    // ---- prologue: weight split ----
    for (int i = tid; i < 64 * 128; i += 512) {
        int t = i >> 7, c = i & 127;
        unsigned short h0, l0, h1, l1;
        bf16_split(W[(2 * t) * 128 + c], h0, l0);
        bf16_split(W[(2 * t + 1) * 128 + c], h1, l1);
        Wh[t * SPW + c] = pack16(h0, h1);
        Wl[t * SPW + c] = pack16(l0, l1);
    }
    if (tid < 128) bs[tid] = b[tid];

    int bstart = blockIdx.x * rpb;
    int bend   = min(bstart + rpb, NN);
    int rb = wr * 16;
    int cb = wc * 32;
    int pbuf = 0;

    // ---- stage tile 0 into buf0 ----
    if (bstart < bend) {
#pragma unroll
        for (int i = 0; i < 4; i++) {
            int rl  = warp * 4 + i;
            int row = bstart + rl;
            float4 v = make_float4(0.f, 0.f, 0.f, 0.f);
            if (row < bend) v = *(const float4*)(src + row * FD + lane * 4);
            split_store4(zhB[0], zlB[0], rl * SPZ + 2 * lane, v);
        }
    }
    __syncthreads();

    for (int tb = bstart; tb < bend; tb += 64) {
        u32* zh = zhB[pbuf];
        u32* zl = zlB[pbuf];
        u32* zhn = zhB[pbuf ^ 1];
        u32* zln = zlB[pbuf ^ 1];
        bool hasNext = (tb + 64) < bend;

        // ---- prefetch next tile rows into registers ----
        float4 vN[4];
        if (hasNext) {
#pragma unroll
            for (int i = 0; i < 4; i++) {
                int row = tb + 64 + warp * 4 + i;
                float4 v = make_float4(0.f, 0.f, 0.f, 0.f);
                if (row < bend) v = *(const float4*)(src + row * FD + lane * 4);
                vN[i] = v;
            }
        }

        // ---- MMA (covers prefetch latency) ----
        float acc[4][4];
#pragma unroll
        for (int j = 0; j < 4; j++)
#pragma unroll
            for (int q = 0; q < 4; q++) acc[j][q] = 0.f;

#pragma unroll 1
        for (int ks = 0; ks < 8; ks++) {
            int ko = ks * 8;
            u32 ah0 = zh[(rb + g) * SPZ + ko + tg];
            u32 ah1 = zh[(rb + 8 + g) * SPZ + ko + tg];
            u32 ah2 = zh[(rb + g) * SPZ + ko + 4 + tg];
            u32 ah3 = zh[(rb + 8 + g) * SPZ + ko + 4 + tg];
            u32 al0 = zl[(rb + g) * SPZ + ko + tg];
            u32 al1 = zl[(rb + 8 + g) * SPZ + ko + tg];
            u32 al2 = zl[(rb + g) * SPZ + ko + 4 + tg];
            u32 al3 = zl[(rb + 8 + g) * SPZ + ko + 4 + tg];
#pragma unroll
            for (int j = 0; j < 4; j++) {
                int c0 = cb + j * 8 + g;
                u32 bh0 = Wh[(ko + tg) * SPW + c0];
                u32 bh1 = Wh[(ko + 4 + tg) * SPW + c0];
                u32 bl0 = Wl[(ko + tg) * SPW + c0];
                u32 bl1 = Wl[(ko + 4 + tg) * SPW + c0];
                mma16816(acc[j][0], acc[j][1], acc[j][2], acc[j][3],
                         ah0, ah1, ah2, ah3, bh0, bh1);
                mma16816(acc[j][0], acc[j][1], acc[j][2], acc[j][3],
                         ah0, ah1, ah2, ah3, bl0, bl1);
                mma16816(acc[j][0], acc[j][1], acc[j][2], acc[j][3],
                         al0, al1, al2, al3, bh0, bh1);
            }
        }

        // ---- split & store next tile ----
        if (hasNext) {
#pragma unroll
            for (int i = 0; i < 4; i++) {
                int rl = warp * 4 + i;
                split_store4(zhn, zln, rl * SPZ + 2 * lane, vN[i]);
            }
        }

        // ---- epilogue ----
        {
            int r0 = tb + rb + g;
            int r1 = tb + rb + 8 + g;
#pragma unroll
            for (int j = 0; j < 4; j++) {
                int col0 = cb + j * 8 + 2 * tg;
                float2 bb = make_float2(0.f, 0.f);
                if (!ADD) bb = *(float2*)(bs + col0);
                if (r0 < bend) {
                    float2* op = (float2*)(out + r0 * FD + col0);
                    float2 o;
                    if (ADD) {
                        float2 prev = *op;
                        o.x = acc[j][0] + prev.x;
                        o.y = acc[j][1] + prev.y;
                    } else {
                        o.x = acc[j][0] + bb.x;
                        o.y = acc[j][1] + bb.y;
                    }
                    if (RELU) { o.x = fmaxf(o.x, 0.f); o.y = fmaxf(o.y, 0.f); }
                    *op = o;
                }
                if (r1 < bend) {
                    float2* op = (float2*)(out + r1 * FD + col0);
                    float2 o;
                    if (ADD) {
                        float2 prev = *op;
                        o.x = acc[j][2] + prev.x;
                        o.y = acc[j][3] + prev.y;
                    } else {
                        o.x = acc[j][2] + bb.x;
                        o.y = acc[j][3] + bb.y;
                    }
                    if (RELU) { o.x = fmaxf(o.x, 0.f); o.y = fmaxf(o.y, 0.f); }
                    *op = o;
                }
            }
        }
        __syncthreads();
        pbuf ^= 1;
    }
}

// ============================================================================
// Decoder via mma.sync, DOUBLE-BUFFERED z staging.
// ============================================================================
#define PW 136
#define PZ 68
#define OFF_W1H 0
#define OFF_W1L (OFF_W1H + 64 * PW)
#define OFF_W2H (OFF_W1L + 64 * PW)
#define OFF_W2L (OFF_W2H + 64 * PW)
#define OFF_ZH0 (OFF_W2L + 64 * PW)
#define OFF_ZL0 (OFF_ZH0 + 64 * PZ)
#define OFF_ZH1 (OFF_ZL0 + 64 * PZ)
#define OFF_ZL1 (OFF_ZH1 + 64 * PZ)
#define OFF_B1  (OFF_ZL1 + 64 * PZ)
#define OFF_B2  (OFF_B1 + 128)
#define OFF_W3  (OFF_B2 + 128)
#define OFF_RED (OFF_W3 + 128)
#define DEC_U32 (OFF_RED + 64 * 4)

__global__ void __launch_bounds__(512, 1)
decoder_kernel(const float* __restrict__ h,
               const int* __restrict__ ps, const int* __restrict__ pd,
               const int* __restrict__ ns, const int* __restrict__ nd,
               const float* __restrict__ Wd1, const float* __restrict__ bd1,
               const float* __restrict__ Wd2, const float* __restrict__ bd2,
               const float* __restrict__ Wd3, const float* __restrict__ bd3,
               float* __restrict__ out,
               int rpb)
{
    extern __shared__ u32 smu[];
    u32* W1h = smu + OFF_W1H;
    u32* W1l = smu + OFF_W1L;
    u32* W2h = smu + OFF_W2H;
    u32* W2l = smu + OFF_W2L;
    u32* zhB[2] = { smu + OFF_ZH0, smu + OFF_ZH1 };
    u32* zlB[2] = { smu + OFF_ZL0, smu + OFF_ZL1 };
    float* b1s = (float*)(smu + OFF_B1);
    float* b2s = (float*)(smu + OFF_B2);
    float* w3s = (float*)(smu + OFF_W3);
    float* red = (float*)(smu + OFF_RED);

    int tid  = threadIdx.x;
    int lane = tid & 31;
    int warp = tid >> 5;
    int g    = lane >> 2;
    int tg   = lane & 3;
    int wr   = warp & 3;
    int wc   = warp >> 2;

    for (int i = tid; i < 64 * 128; i += 512) {
        int t = i >> 7, c = i & 127;
        unsigned short h0, l0, h1, l1;
        float a0 = Wd1[(2 * t) * 128 + c], a1 = Wd1[(2 * t + 1) * 128 + c];
        bf16_split(a0, h0, l0); bf16_split(a1, h1, l1);
        W1h[t * PW + c] = pack16(h0, h1);
        W1l[t * PW + c] = pack16(l0, l1);
        float b0f = Wd2[(2 * t) * 128 + c], b1f = Wd2[(2 * t + 1) * 128 + c];
        bf16_split(b0f, h0, l0); bf16_split(b1f, h1, l1);
        W2h[t * PW + c] = pack16(h0, h1);
        W2l[t * PW + c] = pack16(l0, l1);
    }
    if (tid < 128) {
        b1s[tid] = bd1[tid];
        b2s[tid] = bd2[tid];
        w3s[tid] = Wd3[tid];
    }

    const float b3 = bd3[0];
    const int total = 2 * PP;
    int bstart = blockIdx.x * rpb;
    int bend   = min(bstart + rpb, total);
    int rb = wr * 16;
    int cb = wc * 32;
    int pbuf = 0;

    // ---- stage tile 0 into buf0 ----
    if (bstart < bend) {
#pragma unroll
        for (int i = 0; i < 4; i++) {
            int rl = warp * 4 + i;
            int p  = bstart + rl;
            float4 v = make_float4(0.f, 0.f, 0.f, 0.f);
            if (p < total) {
                int s, d;
                if (p < PP) { s = ps[p]; d = pd[p]; }
                else        { s = ns[p - PP]; d = nd[p - PP]; }
                float4 a = *(const float4*)(h + s * FD + lane * 4);
                float4 c = *(const float4*)(h + d * FD + lane * 4);
                v.x = a.x * c.x; v.y = a.y * c.y;
                v.z = a.z * c.z; v.w = a.w * c.w;
            }
            split_store4(zhB[0], zlB[0], rl * PZ + 2 * lane, v);
        }
    }
    __syncthreads();

    for (int tb = bstart; tb < bend; tb += 64) {
        u32* zh  = zhB[pbuf];
        u32* zl  = zlB[pbuf];
        u32* zhn = zhB[pbuf ^ 1];
        u32* zln = zlB[pbuf ^ 1];
        bool hasNext = (tb + 64) < bend;

        // ---- prefetch next tile products into registers ----
        float4 vN[4];
        if (hasNext) {
#pragma unroll
            for (int i = 0; i < 4; i++) {
                int p = tb + 64 + warp * 4 + i;
                float4 v = make_float4(0.f, 0.f, 0.f, 0.f);
                if (p < total) {
                    int s, d;
                    if (p < PP) { s = ps[p]; d = pd[p]; }
                    else        { s = ns[p - PP]; d = nd[p - PP]; }
                    float4 a = *(const float4*)(h + s * FD + lane * 4);
                    float4 c = *(const float4*)(h + d * FD + lane * 4);
                    v.x = a.x * c.x; v.y = a.y * c.y;
                    v.z = a.z * c.z; v.w = a.w * c.w;
                }
                vN[i] = v;
            }
        }

        float acc[4][4];

        // ================= GEMV 1 (covers prefetch latency) =================
#pragma unroll
        for (int j = 0; j < 4; j++)
#pragma unroll
            for (int q = 0; q < 4; q++) acc[j][q] = 0.f;

#pragma unroll 1
        for (int ks = 0; ks < 8; ks++) {
            int ko = ks * 8;
            u32 ah0 = zh[(rb + g) * PZ + ko + tg];
            u32 ah1 = zh[(rb + 8 + g) * PZ + ko + tg];
            u32 ah2 = zh[(rb + g) * PZ + ko + 4 + tg];
            u32 ah3 = zh[(rb + 8 + g) * PZ + ko + 4 + tg];
            u32 al0 = zl[(rb + g) * PZ + ko + tg];
            u32 al1 = zl[(rb + 8 + g) * PZ + ko + tg];
            u32 al2 = zl[(rb + g) * PZ + ko + 4 + tg];
            u32 al3 = zl[(rb + 8 + g) * PZ + ko + 4 + tg];
#pragma unroll
            for (int j = 0; j < 4; j++) {
                int c0 = cb + j * 8 + g;
                u32 bh0 = W1h[(ko + tg) * PW + c0];
                u32 bh1 = W1h[(ko + 4 + tg) * PW + c0];
                u32 bl0 = W1l[(ko + tg) * PW + c0];
                u32 bl1 = W1l[(ko + 4 + tg) * PW + c0];
                mma16816(acc[j][0], acc[j][1], acc[j][2], acc[j][3],
                         ah0, ah1, ah2, ah3, bh0, bh1);
                mma16816(acc[j][0], acc[j][1], acc[j][2], acc[j][3],
                         ah0, ah1, ah2, ah3, bl0, bl1);
                mma16816(acc[j][0], acc[j][1], acc[j][2], acc[j][3],
                         al0, al1, al2, al3, bh0, bh1);
            }
        }

        // ---- split & store next tile (other buffer) ----
        if (hasNext) {
#pragma unroll
            for (int i = 0; i < 4; i++) {
                int rl = warp * 4 + i;
                split_store4(zhn, zln, rl * PZ + 2 * lane, vN[i]);
            }
        }
        __syncthreads();   // GEMV1 reads of zh done; next buffer staged

        // ---- t1 = relu(acc + b1), restage into current buffer ----
#pragma unroll
        for (int j = 0; j < 4; j++) {
            int col0 = cb + j * 8 + 2 * tg;
            float t0 = fmaxf(acc[j][0] + b1s[col0],     0.f);
            float t1 = fmaxf(acc[j][1] + b1s[col0 + 1], 0.f);
            float t2 = fmaxf(acc[j][2] + b1s[col0],     0.f);
            float t3 = fmaxf(acc[j][3] + b1s[col0 + 1], 0.f);
            unsigned short h0, l0, h1, l1;
            int t2i = col0 >> 1;
            bf16_split(t0, h0, l0); bf16_split(t1, h1, l1);
            zh[(rb + g) * PZ + t2i] = pack16(h0, h1);
            zl[(rb + g) * PZ + t2i] = pack16(l0, l1);
            bf16_split(t2, h0, l0); bf16_split(t3, h1, l1);
            zh[(rb + 8 + g) * PZ + t2i] = pack16(h0, h1);
            zl[(rb + 8 + g) * PZ + t2i] = pack16(l0, l1);
        }
        __syncthreads();

        // ================= GEMV 2 =================
#pragma unroll
        for (int j = 0; j < 4; j++)
#pragma unroll
            for (int q = 0; q < 4; q++) acc[j][q] = 0.f;

#pragma unroll 1
        for (int ks = 0; ks < 8; ks++) {
            int ko = ks * 8;
            u32 ah0 = zh[(rb + g) * PZ + ko + tg];
            u32 ah1 = zh[(rb + 8 + g) * PZ + ko + tg];
            u32 ah2 = zh[(rb + g) * PZ + ko + 4 + tg];
            u32 ah3 = zh[(rb + 8 + g) * PZ + ko + 4 + tg];
            u32 al0 = zl[(rb + g) * PZ + ko + tg];
            u32 al1 = zl[(rb + 8 + g) * PZ + ko + tg];
            u32 al2 = zl[(rb + g) * PZ + ko + 4 + tg];
            u32 al3 = zl[(rb + 8 + g) * PZ + ko + 4 + tg];
#pragma unroll
            for (int j = 0; j < 4; j++) {
                int c0 = cb + j * 8 + g;
                u32 bh0 = W2h[(ko + tg) * PW + c0];
                u32 bh1 = W2h[(ko + 4 + tg) * PW + c0];
                u32 bl0 = W2l[(ko + tg) * PW + c0];
                u32 bl1 = W2l[(ko + 4 + tg) * PW + c0];
                mma16816(acc[j][0], acc[j][1], acc[j][2], acc[j][3],
                         ah0, ah1, ah2, ah3, bh0, bh1);
                mma16816(acc[j][0], acc[j][1], acc[j][2], acc[j][3],
                         ah0, ah1, ah2, ah3, bl0, bl1);
                mma16816(acc[j][0], acc[j][1], acc[j][2], acc[j][3],
                         al0, al1, al2, al3, bh0, bh1);
            }
        }

        // ---- out = relu(acc + b2) . Wd3 + bd3 ----
        {
            float pr0 = 0.f, pr1 = 0.f;
#pragma unroll
            for (int j = 0; j < 4; j++) {
                int col0 = cb + j * 8 + 2 * tg;
                float wa = w3s[col0], wb = w3s[col0 + 1];
                pr0 += fmaxf(acc[j][0] + b2s[col0],     0.f) * wa
                     + fmaxf(acc[j][1] + b2s[col0 + 1], 0.f) * wb;
                pr1 += fmaxf(acc[j][2] + b2s[col0],     0.f) * wa
                     + fmaxf(acc[j][3] + b2s[col0 + 1], 0.f) * wb;
            }
            pr0 += __shfl_xor_sync(0xffffffffu, pr0, 1);
            pr0 += __shfl_xor_sync(0xffffffffu, pr0, 2);
            pr1 += __shfl_xor_sync(0xffffffffu, pr1, 1);
            pr1 += __shfl_xor_sync(0xffffffffu, pr1, 2);
            if (tg == 0) {
                red[(rb + g) * 4 + wc]     = pr0;
                red[(rb + 8 + g) * 4 + wc] = pr1;
            }
        }
        __syncthreads();

        if (tid < 64) {
            int p = tb + tid;
            if (p < total)
                out[p] = red[tid * 4] + red[tid * 4 + 1]
                       + red[tid * 4 + 2] + red[tid * 4 + 3] + b3;
        }
        __syncthreads();
        pbuf ^= 1;
    }
}

// ============================================================================
// launch — two-stream fork/join (unchanged)
// ============================================================================
extern "C" void kernel_launch(void* const* d_in, const int* in_sizes, int n_in,
                              void* d_out, int out_size)
{
    const float* x    = (const float*)d_in[0];
    const int*   esrc = (const int*)  d_in[1];
    const int*   edst = (const int*)  d_in[2];
    const int*   ps   = (const int*)  d_in[3];
    const int*   pd   = (const int*)  d_in[4];
    const int*   ns   = (const int*)  d_in[5];
    const int*   nd   = (const int*)  d_in[6];
    const float* Ws1  = (const float*)d_in[7];
    const float* Wn1  = (const float*)d_in[8];
    const float* b1   = (const float*)d_in[9];
    const float* Ws2  = (const float*)d_in[10];
    const float* Wn2  = (const float*)d_in[11];
    const float* b2   = (const float*)d_in[12];
    const float* Wd1  = (const float*)d_in[13];
    const float* bd1  = (const float*)d_in[14];
    const float* Wd2  = (const float*)d_in[15];
    const float* bd2  = (const float*)d_in[16];
    const float* Wd3  = (const float*)d_in[17];
    const float* bd3  = (const float*)d_in[18];
    float* out = (float*)d_out;

    void *aggPtr, *h1Ptr, *h2Ptr;
    cudaGetSymbolAddress(&aggPtr, g_agg);
    cudaGetSymbolAddress(&h1Ptr,  g_h1);
    cudaGetSymbolAddress(&h2Ptr,  g_h2);
    float* h1 = (float*)h1Ptr;
    float* h2 = (float*)h2Ptr;
    float* agg = (float*)aggPtr;

    int nsm = 148;
    cudaDeviceGetAttribute(&nsm, cudaDevAttrMultiProcessorCount, 0);

    int rpb_sage = (((NN + nsm - 1) / nsm) + 63) & ~63;
    int rpb_dec  = (((2 * PP + nsm - 1) / nsm) + 63) & ~63;

    const int SAGE_SMEM = SAGE_U32 * 4;    // ~136.5 KB
    const int DEC_SMEM  = DEC_U32 * 4;     // ~206.5 KB
    cudaFuncSetAttribute(sage_half_mma<false, false>,
                         cudaFuncAttributeMaxDynamicSharedMemorySize, SAGE_SMEM);
    cudaFuncSetAttribute(sage_half_mma<true, true>,
                         cudaFuncAttributeMaxDynamicSharedMemorySize, SAGE_SMEM);
    cudaFuncSetAttribute(sage_half_mma<true, false>,
                         cudaFuncAttributeMaxDynamicSharedMemorySize, SAGE_SMEM);
    cudaFuncSetAttribute(decoder_kernel,
                         cudaFuncAttributeMaxDynamicSharedMemorySize, DEC_SMEM);

    static cudaStream_t sB = nullptr;
    static cudaEvent_t evFork = nullptr, evAgg1 = nullptr,
                       evH1 = nullptr, evAgg2 = nullptr;
    if (sB == nullptr) {
        cudaStreamCreateWithFlags(&sB, cudaStreamNonBlocking);
        cudaEventCreateWithFlags(&evFork, cudaEventDisableTiming);
        cudaEventCreateWithFlags(&evAgg1, cudaEventDisableTiming);
        cudaEventCreateWithFlags(&evH1,   cudaEventDisableTiming);
        cudaEventCreateWithFlags(&evAgg2, cudaEventDisableTiming);
    }

    int ablocks = (NN * 32 + 255) / 256;

    // ---- fork ----
    cudaEventRecord(evFork, 0);
    cudaStreamWaitEvent(sB, evFork, 0);

    // streamB: CSR build + aggregate layer 1
    count_kernel<<<(EE + 255) / 256, 256, 0, sB>>>(edst);
    scan_kernel<<<1, 1024, 0, sB>>>();
    fill_kernel<<<(EE + 255) / 256, 256, 0, sB>>>(esrc, edst);
    aggregate_kernel<<<ablocks, 256, 0, sB>>>(x);
    cudaEventRecord(evAgg1, sB);

    // streamA: self half of layer 1 (concurrent with CSR+agg1)
    sage_half_mma<false, false><<<nsm, 512, SAGE_SMEM>>>(x, Ws1, b1, h1,
                                                         rpb_sage);
    cudaStreamWaitEvent(0, evAgg1, 0);
    sage_half_mma<true, true><<<nsm, 512, SAGE_SMEM>>>(agg, Wn1, b1, h1,
                                                       rpb_sage);
    cudaEventRecord(evH1, 0);

    // streamB: aggregate layer 2 (concurrent with sage2_self)
    cudaStreamWaitEvent(sB, evH1, 0);
    aggregate_kernel<<<ablocks, 256, 0, sB>>>(h1);
    cudaEventRecord(evAgg2, sB);

    // streamA: self half of layer 2
    sage_half_mma<false, false><<<nsm, 512, SAGE_SMEM>>>(h1, Ws2, b2, h2,
                                                         rpb_sage);
    cudaStreamWaitEvent(0, evAgg2, 0);
    sage_half_mma<true, false><<<nsm, 512, SAGE_SMEM>>>(agg, Wn2, b2, h2,
                                                        rpb_sage);

    // decoder
    decoder_kernel<<<nsm, 512, DEC_SMEM>>>(h2, ps, pd, ns, nd,
                                           Wd1, bd1, Wd2, bd2, Wd3, bd3, out,
                                           rpb_dec);
}

// round 15
// speedup vs baseline: 1.0786x; 1.0786x over previous
#include <cuda_runtime.h>
#include <cuda_bf16.h>
#include <cstdint>

#define NN 50000
#define EE 600000
#define PP 100000
#define FD 128

// ---- device scratch ----
__device__ float g_agg[NN * FD];
__device__ float g_h1[NN * FD];
__device__ float g_h2[NN * FD];
__device__ int   g_cnt[NN];          // restored to 0 by fill_kernel each run
__device__ int   g_rowstart[NN + 1];
__device__ int   g_csr[EE];

typedef unsigned long long u64;
typedef unsigned int u32;

// bf16 split helpers
__device__ __forceinline__ void bf16_split(float x, unsigned short& h, unsigned short& l) {
    __nv_bfloat16 bh = __float2bfloat16(x);
    float r = x - __bfloat162float(bh);
    __nv_bfloat16 bl = __float2bfloat16(r);
    h = __bfloat16_as_ushort(bh);
    l = __bfloat16_as_ushort(bl);
}
__device__ __forceinline__ u32 pack16(unsigned short lo, unsigned short hi) {
    return (u32)lo | ((u32)hi << 16);
}

// m16n8k16 bf16 MMA, f32 accum
__device__ __forceinline__ void mma16816(float& c0, float& c1, float& c2, float& c3,
                                         u32 a0, u32 a1, u32 a2, u32 a3,
                                         u32 b0, u32 b1) {
    asm volatile(
        "mma.sync.aligned.m16n8k16.row.col.f32.bf16.bf16.f32 "
        "{%0,%1,%2,%3}, {%4,%5,%6,%7}, {%8,%9}, {%0,%1,%2,%3};"
        : "+f"(c0), "+f"(c1), "+f"(c2), "+f"(c3)
        : "r"(a0), "r"(a1), "r"(a2), "r"(a3), "r"(b0), "r"(b1));
}

// ============================================================================
// CSR build (proven)
// ============================================================================
__global__ void count_kernel(const int* __restrict__ dst)
{
    int e = blockIdx.x * blockDim.x + threadIdx.x;
    if (e < EE) atomicAdd(&g_cnt[dst[e]], 1);
}

__global__ void __launch_bounds__(1024, 1) scan_kernel()
{
    __shared__ int wsum[32];
    __shared__ int carry;
    int tid = threadIdx.x, lane = tid & 31, w = tid >> 5;
    if (tid == 0) carry = 0;
    __syncthreads();
    for (int base = 0; base < NN; base += 1024) {
        int i = base + tid;
        int v = (i < NN) ? g_cnt[i] : 0;
        int s = v;
#pragma unroll
        for (int off = 1; off < 32; off <<= 1) {
            int t = __shfl_up_sync(0xffffffffu, s, off);
            if (lane >= off) s += t;
        }
        if (lane == 31) wsum[w] = s;
        __syncthreads();
        if (w == 0) {
            int ws = wsum[lane];
#pragma unroll
            for (int off = 1; off < 32; off <<= 1) {
                int t = __shfl_up_sync(0xffffffffu, ws, off);
                if (lane >= off) ws += t;
            }
            wsum[lane] = ws;
        }
        __syncthreads();
        int prev = (w > 0) ? wsum[w - 1] : 0;
        int incl = carry + prev + s;
        if (i < NN) g_rowstart[i + 1] = incl;
        int chunk_total = wsum[31];
        __syncthreads();
        if (tid == 0) carry += chunk_total;
        __syncthreads();
    }
    if (threadIdx.x == 0) g_rowstart[0] = 0;
}

__global__ void fill_kernel(const int* __restrict__ src,
                            const int* __restrict__ dst)
{
    int e = blockIdx.x * blockDim.x + threadIdx.x;
    if (e >= EE) return;
    int d = dst[e];
    int p = atomicAdd(&g_cnt[d], -1) - 1;
    g_csr[g_rowstart[d] + p] = src[e];
}

// ============================================================================
// Aggregate (proven)
// ============================================================================
__global__ void aggregate_kernel(const float* __restrict__ h)
{
    int gw   = (blockIdx.x * blockDim.x + threadIdx.x) >> 5;
    int lane = threadIdx.x & 31;
    if (gw >= NN) return;
    int beg = g_rowstart[gw], end = g_rowstart[gw + 1];
    const float* hp = h + lane * 4;
    float4 acc = make_float4(0.f, 0.f, 0.f, 0.f);
    int e = beg;
    for (; e + 1 < end; e += 2) {
        int s0 = g_csr[e], s1 = g_csr[e + 1];
        float4 v0 = *(const float4*)(hp + s0 * FD);
        float4 v1 = *(const float4*)(hp + s1 * FD);
        acc.x += v0.x + v1.x; acc.y += v0.y + v1.y;
        acc.z += v0.z + v1.z; acc.w += v0.w + v1.w;
    }
    if (e < end) {
        int s0 = g_csr[e];
        float4 v0 = *(const float4*)(hp + s0 * FD);
        acc.x += v0.x; acc.y += v0.y; acc.z += v0.z; acc.w += v0.w;
    }
    float rd = 1.0f / fmaxf((float)(end - beg), 1.0f);
    acc.x *= rd; acc.y *= rd; acc.z *= rd; acc.w *= rd;
    *(float4*)(g_agg + gw * FD + lane * 4) = acc;
}

// ============================================================================
// Half-K SAGE linear via mma.sync (R13 form, FROZEN)
// ============================================================================
#define SPW 136
#define SPZ 68
#define OFF_SWH 0
#define OFF_SWL (OFF_SWH + 64 * SPW)
#define OFF_SZH (OFF_SWL + 64 * SPW)
#define OFF_SZL (OFF_SZH + 64 * SPZ)
#define OFF_SB  (OFF_SZL + 64 * SPZ)
#define SAGE_U32 (OFF_SB + 128)

template <bool ADD, bool RELU>
__global__ void __launch_bounds__(512, 1)
sage_half_mma(const float* __restrict__ src,
              const float* __restrict__ W,
              const float* __restrict__ b,
              float* __restrict__ out,
              int rpb)
{
    extern __shared__ u32 smu[];
    u32* Wh = smu + OFF_SWH;
    u32* Wl = smu + OFF_SWL;
    u32* zh = smu + OFF_SZH;
    u32* zl = smu + OFF_SZL;
    float* bs = (float*)(smu + OFF_SB);

    int tid  = threadIdx.x;
    int lane = tid & 31;
    int warp = tid >> 5;
    int g    = lane >> 2;
    int tg   = lane & 3;
    int wr   = warp & 3;
    int wc   = warp >> 2;

    for (int i = tid; i < 64 * 128; i += 512) {
        int t = i >> 7, c = i & 127;
        unsigned short h0, l0, h1, l1;
        bf16_split(W[(2 * t) * 128 + c], h0, l0);
        bf16_split(W[(2 * t + 1) * 128 + c], h1, l1);
        Wh[t * SPW + c] = pack16(h0, h1);
        Wl[t * SPW + c] = pack16(l0, l1);
    }
    if (tid < 128) bs[tid] = b[tid];
    __syncthreads();

    int bstart = blockIdx.x * rpb;
    int bend   = min(bstart + rpb, NN);
    int rb = wr * 16;
    int cb = wc * 32;

    for (int tb = bstart; tb < bend; tb += 64) {

#pragma unroll
        for (int i = 0; i < 4; i++) {
            int rl  = warp * 4 + i;
            int row = tb + rl;
            float4 v = make_float4(0.f, 0.f, 0.f, 0.f);
            if (row < bend)
                v = *(const float4*)(src + row * FD + lane * 4);
            unsigned short h0, l0, h1, l1, h2_, l2_, h3_, l3_;
            bf16_split(v.x, h0, l0); bf16_split(v.y, h1, l1);
            bf16_split(v.z, h2_, l2_); bf16_split(v.w, h3_, l3_);
            u32 base_ = rl * SPZ + 2 * lane;
            *(uint2*)(zh + base_) = make_uint2(pack16(h0, h1), pack16(h2_, h3_));
            *(uint2*)(zl + base_) = make_uint2(pack16(l0, l1), pack16(l2_, l3_));
        }
        __syncthreads();

        float acc[4][4];
#pragma unroll
        for (int j = 0; j < 4; j++)
#pragma unroll
            for (int q = 0; q < 4; q++) acc[j][q] = 0.f;

#pragma unroll 1
        for (int ks = 0; ks < 8; ks++) {
            int ko = ks * 8;
            u32 ah0 = zh[(rb + g) * SPZ + ko + tg];
            u32 ah1 = zh[(rb + 8 + g) * SPZ + ko + tg];
            u32 ah2 = zh[(rb + g) * SPZ + ko + 4 + tg];
            u32 ah3 = zh[(rb + 8 + g) * SPZ + ko + 4 + tg];
            u32 al0 = zl[(rb + g) * SPZ + ko + tg];
            u32 al1 = zl[(rb + 8 + g) * SPZ + ko + tg];
            u32 al2 = zl[(rb + g) * SPZ + ko + 4 + tg];
            u32 al3 = zl[(rb + 8 + g) * SPZ + ko + 4 + tg];
#pragma unroll
            for (int j = 0; j < 4; j++) {
                int c0 = cb + j * 8 + g;
                u32 bh0 = Wh[(ko + tg) * SPW + c0];
                u32 bh1 = Wh[(ko + 4 + tg) * SPW + c0];
                u32 bl0 = Wl[(ko + tg) * SPW + c0];
                u32 bl1 = Wl[(ko + 4 + tg) * SPW + c0];
                mma16816(acc[j][0], acc[j][1], acc[j][2], acc[j][3],
                         ah0, ah1, ah2, ah3, bh0, bh1);
                mma16816(acc[j][0], acc[j][1], acc[j][2], acc[j][3],
                         ah0, ah1, ah2, ah3, bl0, bl1);
                mma16816(acc[j][0], acc[j][1], acc[j][2], acc[j][3],
                         al0, al1, al2, al3, bh0, bh1);
            }
        }

        {
            int r0 = tb + rb + g;
            int r1 = tb + rb + 8 + g;
#pragma unroll
            for (int j = 0; j < 4; j++) {
                int col0 = cb + j * 8 + 2 * tg;
                float2 bb = make_float2(0.f, 0.f);
                if (!ADD) bb = *(float2*)(bs + col0);
                if (r0 < bend) {
                    float2* op = (float2*)(out + r0 * FD + col0);
                    float2 o;
                    if (ADD) {
                        float2 prev = *op;
                        o.x = acc[j][0] + prev.x;
                        o.y = acc[j][1] + prev.y;
                    } else {
                        o.x = acc[j][0] + bb.x;
                        o.y = acc[j][1] + bb.y;
                    }
                    if (RELU) { o.x = fmaxf(o.x, 0.f); o.y = fmaxf(o.y, 0.f); }
                    *op = o;
                }
                if (r1 < bend) {
                    float2* op = (float2*)(out + r1 * FD + col0);
                    float2 o;
                    if (ADD) {
                        float2 prev = *op;
                        o.x = acc[j][2] + prev.x;
                        o.y = acc[j][3] + prev.y;
                    } else {
                        o.x = acc[j][2] + bb.x;
                        o.y = acc[j][3] + bb.y;
                    }
                    if (RELU) { o.x = fmaxf(o.x, 0.f); o.y = fmaxf(o.y, 0.f); }
                    *op = o;
                }
            }
        }
        __syncthreads();
    }
}

// ============================================================================
// Decoder via mma.sync, 128-row double-tile per iteration.
// Two 64-row sub-tiles share weight fragments and barriers.
// ============================================================================
#define PW 136
#define PZ 68
#define OFF_W1H 0
#define OFF_W1L (OFF_W1H + 64 * PW)
#define OFF_W2H (OFF_W1L + 64 * PW)
#define OFF_W2L (OFF_W2H + 64 * PW)
#define OFF_ZH  (OFF_W2L + 64 * PW)
#define OFF_ZL  (OFF_ZH + 128 * PZ)
#define OFF_B1  (OFF_ZL + 128 * PZ)
#define OFF_B2  (OFF_B1 + 128)
#define OFF_W3  (OFF_B2 + 128)
#define OFF_RED (OFF_W3 + 128)
#define DEC_U32 (OFF_RED + 128 * 4)

__global__ void __launch_bounds__(512, 1)
decoder_kernel(const float* __restrict__ h,
               const int* __restrict__ ps, const int* __restrict__ pd,
               const int* __restrict__ ns, const int* __restrict__ nd,
               const float* __restrict__ Wd1, const float* __restrict__ bd1,
               const float* __restrict__ Wd2, const float* __restrict__ bd2,
               const float* __restrict__ Wd3, const float* __restrict__ bd3,
               float* __restrict__ out,
               int rpb)
{
    extern __shared__ u32 smu[];
    u32* W1h = smu + OFF_W1H;
    u32* W1l = smu + OFF_W1L;
    u32* W2h = smu + OFF_W2H;
    u32* W2l = smu + OFF_W2L;
    u32* zh  = smu + OFF_ZH;   // [128][PZ]
    u32* zl  = smu + OFF_ZL;   // [128][PZ]
    float* b1s = (float*)(smu + OFF_B1);
    float* b2s = (float*)(smu + OFF_B2);
    float* w3s = (float*)(smu + OFF_W3);
    float* red = (float*)(smu + OFF_RED);   // [128][4]

    int tid  = threadIdx.x;
    int lane = tid & 31;
    int warp = tid >> 5;
    int g    = lane >> 2;
    int tg   = lane & 3;
    int wr   = warp & 3;
    int wc   = warp >> 2;

    for (int i = tid; i < 64 * 128; i += 512) {
        int t = i >> 7, c = i & 127;
        unsigned short h0, l0, h1, l1;
        float a0 = Wd1[(2 * t) * 128 + c], a1 = Wd1[(2 * t + 1) * 128 + c];
        bf16_split(a0, h0, l0); bf16_split(a1, h1, l1);
        W1h[t * PW + c] = pack16(h0, h1);
        W1l[t * PW + c] = pack16(l0, l1);
        float b0f = Wd2[(2 * t) * 128 + c], b1f = Wd2[(2 * t + 1) * 128 + c];
        bf16_split(b0f, h0, l0); bf16_split(b1f, h1, l1);
        W2h[t * PW + c] = pack16(h0, h1);
        W2l[t * PW + c] = pack16(l0, l1);
    }
    if (tid < 128) {
        b1s[tid] = bd1[tid];
        b2s[tid] = bd2[tid];
        w3s[tid] = Wd3[tid];
    }
    __syncthreads();

    const float b3 = bd3[0];
    const int total = 2 * PP;
    int bstart = blockIdx.x * rpb;
    int bend   = min(bstart + rpb, total);
    int rb = wr * 16;
    int cb = wc * 32;

    for (int tb = bstart; tb < bend; tb += 128) {

        // ---- stage 128 pair-rows: z = h[s]*h[d], bf16 split ----
#pragma unroll
        for (int i = 0; i < 8; i++) {
            int rl = warp * 8 + i;          // 0..127
            int p  = tb + rl;
            float4 v = make_float4(0.f, 0.f, 0.f, 0.f);
            if (p < total) {
                int s, d;
                if (p < PP) { s = ps[p]; d = pd[p]; }
                else        { s = ns[p - PP]; d = nd[p - PP]; }
                float4 a = *(const float4*)(h + s * FD + lane * 4);
                float4 c = *(const float4*)(h + d * FD + lane * 4);
                v.x = a.x * c.x; v.y = a.y * c.y;
                v.z = a.z * c.z; v.w = a.w * c.w;
            }
            unsigned short h0, l0, h1, l1, h2_, l2_, h3_, l3_;
            bf16_split(v.x, h0, l0); bf16_split(v.y, h1, l1);
            bf16_split(v.z, h2_, l2_); bf16_split(v.w, h3_, l3_);
            u32 base_ = rl * PZ + 2 * lane;
            *(uint2*)(zh + base_) = make_uint2(pack16(h0, h1), pack16(h2_, h3_));
            *(uint2*)(zl + base_) = make_uint2(pack16(l0, l1), pack16(l2_, l3_));
        }
        __syncthreads();

        float accA[4][4], accB[4][4];

        // ================= GEMV 1 (both sub-tiles) =================
#pragma unroll
        for (int j = 0; j < 4; j++)
#pragma unroll
            for (int q = 0; q < 4; q++) { accA[j][q] = 0.f; accB[j][q] = 0.f; }

#pragma unroll 1
        for (int ks = 0; ks < 8; ks++) {
            int ko = ks * 8;
            int rA0 = (rb + g) * PZ, rA1 = (rb + 8 + g) * PZ;
            int rB0 = (64 + rb + g) * PZ, rB1 = (64 + rb + 8 + g) * PZ;
            u32 ahA0 = zh[rA0 + ko + tg],     ahA1 = zh[rA1 + ko + tg];
            u32 ahA2 = zh[rA0 + ko + 4 + tg], ahA3 = zh[rA1 + ko + 4 + tg];
            u32 alA0 = zl[rA0 + ko + tg],     alA1 = zl[rA1 + ko + tg];
            u32 alA2 = zl[rA0 + ko + 4 + tg], alA3 = zl[rA1 + ko + 4 + tg];
            u32 ahB0 = zh[rB0 + ko + tg],     ahB1 = zh[rB1 + ko + tg];
            u32 ahB2 = zh[rB0 + ko + 4 + tg], ahB3 = zh[rB1 + ko + 4 + tg];
            u32 alB0 = zl[rB0 + ko + tg],     alB1 = zl[rB1 + ko + tg];
            u32 alB2 = zl[rB0 + ko + 4 + tg], alB3 = zl[rB1 + ko + 4 + tg];
#pragma unroll
            for (int j = 0; j < 4; j++) {
                int c0 = cb + j * 8 + g;
                u32 bh0 = W1h[(ko + tg) * PW + c0];
                u32 bh1 = W1h[(ko + 4 + tg) * PW + c0];
                u32 bl0 = W1l[(ko + tg) * PW + c0];
                u32 bl1 = W1l[(ko + 4 + tg) * PW + c0];
                mma16816(accA[j][0], accA[j][1], accA[j][2], accA[j][3],
                         ahA0, ahA1, ahA2, ahA3, bh0, bh1);
                mma16816(accB[j][0], accB[j][1], accB[j][2], accB[j][3],
                         ahB0, ahB1, ahB2, ahB3, bh0, bh1);
                mma16816(accA[j][0], accA[j][1], accA[j][2], accA[j][3],
                         ahA0, ahA1, ahA2, ahA3, bl0, bl1);
                mma16816(accB[j][0], accB[j][1], accB[j][2], accB[j][3],
                         ahB0, ahB1, ahB2, ahB3, bl0, bl1);
                mma16816(accA[j][0], accA[j][1], accA[j][2], accA[j][3],
                         alA0, alA1, alA2, alA3, bh0, bh1);
                mma16816(accB[j][0], accB[j][1], accB[j][2], accB[j][3],
                         alB0, alB1, alB2, alB3, bh0, bh1);
            }
        }
        __syncthreads();

        // ---- t1 = relu(acc + b1), restage both sub-tiles ----
#pragma unroll
        for (int j = 0; j < 4; j++) {
            int col0 = cb + j * 8 + 2 * tg;
            int t2i = col0 >> 1;
            unsigned short h0, l0, h1, l1;
            float t0 = fmaxf(accA[j][0] + b1s[col0],     0.f);
            float t1 = fmaxf(accA[j][1] + b1s[col0 + 1], 0.f);
            bf16_split(t0, h0, l0); bf16_split(t1, h1, l1);
            zh[(rb + g) * PZ + t2i] = pack16(h0, h1);
            zl[(rb + g) * PZ + t2i] = pack16(l0, l1);
            t0 = fmaxf(accA[j][2] + b1s[col0],     0.f);
            t1 = fmaxf(accA[j][3] + b1s[col0 + 1], 0.f);
            bf16_split(t0, h0, l0); bf16_split(t1, h1, l1);
            zh[(rb + 8 + g) * PZ + t2i] = pack16(h0, h1);
            zl[(rb + 8 + g) * PZ + t2i] = pack16(l0, l1);
            t0 = fmaxf(accB[j][0] + b1s[col0],     0.f);
            t1 = fmaxf(accB[j][1] + b1s[col0 + 1], 0.f);
            bf16_split(t0, h0, l0); bf16_split(t1, h1, l1);
            zh[(64 + rb + g) * PZ + t2i] = pack16(h0, h1);
            zl[(64 + rb + g) * PZ + t2i] = pack16(l0, l1);
            t0 = fmaxf(accB[j][2] + b1s[col0],     0.f);
            t1 = fmaxf(accB[j][3] + b1s[col0 + 1], 0.f);
            bf16_split(t0, h0, l0); bf16_split(t1, h1, l1);
            zh[(64 + rb + 8 + g) * PZ + t2i] = pack16(h0, h1);
            zl[(64 + rb + 8 + g) * PZ + t2i] = pack16(l0, l1);
        }
        __syncthreads();

        // ================= GEMV 2 (both sub-tiles) =================
#pragma unroll
        for (int j = 0; j < 4; j++)
#pragma unroll
            for (int q = 0; q < 4; q++) { accA[j][q] = 0.f; accB[j][q] = 0.f; }

#pragma unroll 1
        for (int ks = 0; ks < 8; ks++) {
            int ko = ks * 8;
            int rA0 = (rb + g) * PZ, rA1 = (rb + 8 + g) * PZ;
            int rB0 = (64 + rb + g) * PZ, rB1 = (64 + rb + 8 + g) * PZ;
            u32 ahA0 = zh[rA0 + ko + tg],     ahA1 = zh[rA1 + ko + tg];
            u32 ahA2 = zh[rA0 + ko + 4 + tg], ahA3 = zh[rA1 + ko + 4 + tg];
            u32 alA0 = zl[rA0 + ko + tg],     alA1 = zl[rA1 + ko + tg];
            u32 alA2 = zl[rA0 + ko + 4 + tg], alA3 = zl[rA1 + ko + 4 + tg];
            u32 ahB0 = zh[rB0 + ko + tg],     ahB1 = zh[rB1 + ko + tg];
            u32 ahB2 = zh[rB0 + ko + 4 + tg], ahB3 = zh[rB1 + ko + 4 + tg];
            u32 alB0 = zl[rB0 + ko + tg],     alB1 = zl[rB1 + ko + tg];
            u32 alB2 = zl[rB0 + ko + 4 + tg], alB3 = zl[rB1 + ko + 4 + tg];
#pragma unroll
            for (int j = 0; j < 4; j++) {
                int c0 = cb + j * 8 + g;
                u32 bh0 = W2h[(ko + tg) * PW + c0];
                u32 bh1 = W2h[(ko + 4 + tg) * PW + c0];
                u32 bl0 = W2l[(ko + tg) * PW + c0];
                u32 bl1 = W2l[(ko + 4 + tg) * PW + c0];
                mma16816(accA[j][0], accA[j][1], accA[j][2], accA[j][3],
                         ahA0, ahA1, ahA2, ahA3, bh0, bh1);
                mma16816(accB[j][0], accB[j][1], accB[j][2], accB[j][3],
                         ahB0, ahB1, ahB2, ahB3, bh0, bh1);
                mma16816(accA[j][0], accA[j][1], accA[j][2], accA[j][3],
                         ahA0, ahA1, ahA2, ahA3, bl0, bl1);
                mma16816(accB[j][0], accB[j][1], accB[j][2], accB[j][3],
                         ahB0, ahB1, ahB2, ahB3, bl0, bl1);
                mma16816(accA[j][0], accA[j][1], accA[j][2], accA[j][3],
                         alA0, alA1, alA2, alA3, bh0, bh1);
                mma16816(accB[j][0], accB[j][1], accB[j][2], accB[j][3],
                         alB0, alB1, alB2, alB3, bh0, bh1);
            }
        }

        // ---- out = relu(acc + b2) . Wd3 + bd3 (both sub-tiles) ----
        {
            float pA0 = 0.f, pA1 = 0.f, pB0 = 0.f, pB1 = 0.f;
#pragma unroll
            for (int j = 0; j < 4; j++) {
                int col0 = cb + j * 8 + 2 * tg;
                float wa = w3s[col0], wb = w3s[col0 + 1];
                pA0 += fmaxf(accA[j][0] + b2s[col0],     0.f) * wa
                     + fmaxf(accA[j][1] + b2s[col0 + 1], 0.f) * wb;
                pA1 += fmaxf(accA[j][2] + b2s[col0],     0.f) * wa
                     + fmaxf(accA[j][3] + b2s[col0 + 1], 0.f) * wb;
                pB0 += fmaxf(accB[j][0] + b2s[col0],     0.f) * wa
                     + fmaxf(accB[j][1] + b2s[col0 + 1], 0.f) * wb;
                pB1 += fmaxf(accB[j][2] + b2s[col0],     0.f) * wa
                     + fmaxf(accB[j][3] + b2s[col0 + 1], 0.f) * wb;
            }
            pA0 += __shfl_xor_sync(0xffffffffu, pA0, 1);
            pA0 += __shfl_xor_sync(0xffffffffu, pA0, 2);
            pA1 += __shfl_xor_sync(0xffffffffu, pA1, 1);
            pA1 += __shfl_xor_sync(0xffffffffu, pA1, 2);
            pB0 += __shfl_xor_sync(0xffffffffu, pB0, 1);
            pB0 += __shfl_xor_sync(0xffffffffu, pB0, 2);
            pB1 += __shfl_xor_sync(0xffffffffu, pB1, 1);
            pB1 += __shfl_xor_sync(0xffffffffu, pB1, 2);
            if (tg == 0) {
                red[(rb + g) * 4 + wc]          = pA0;
                red[(rb + 8 + g) * 4 + wc]      = pA1;
                red[(64 + rb + g) * 4 + wc]     = pB0;
                red[(64 + rb + 8 + g) * 4 + wc] = pB1;
            }
        }
        __syncthreads();

        if (tid < 128) {
            int p = tb + tid;
            if (p < total)
                out[p] = red[tid * 4] + red[tid * 4 + 1]
                       + red[tid * 4 + 2] + red[tid * 4 + 3] + b3;
        }
        __syncthreads();
    }
}

// ============================================================================
// launch — two-stream fork/join (R13 structure)
// ============================================================================
extern "C" void kernel_launch(void* const* d_in, const int* in_sizes, int n_in,
                              void* d_out, int out_size)
{
    const float* x    = (const float*)d_in[0];
    const int*   esrc = (const int*)  d_in[1];
    const int*   edst = (const int*)  d_in[2];
    const int*   ps   = (const int*)  d_in[3];
    const int*   pd   = (const int*)  d_in[4];
    const int*   ns   = (const int*)  d_in[5];
    const int*   nd   = (const int*)  d_in[6];
    const float* Ws1  = (const float*)d_in[7];
    const float* Wn1  = (const float*)d_in[8];
    const float* b1   = (const float*)d_in[9];
    const float* Ws2  = (const float*)d_in[10];
    const float* Wn2  = (const float*)d_in[11];
    const float* b2   = (const float*)d_in[12];
    const float* Wd1  = (const float*)d_in[13];
    const float* bd1  = (const float*)d_in[14];
    const float* Wd2  = (const float*)d_in[15];
    const float* bd2  = (const float*)d_in[16];
    const float* Wd3  = (const float*)d_in[17];
    const float* bd3  = (const float*)d_in[18];
    float* out = (float*)d_out;

    void *aggPtr, *h1Ptr, *h2Ptr;
    cudaGetSymbolAddress(&aggPtr, g_agg);
    cudaGetSymbolAddress(&h1Ptr,  g_h1);
    cudaGetSymbolAddress(&h2Ptr,  g_h2);
    float* h1 = (float*)h1Ptr;
    float* h2 = (float*)h2Ptr;
    float* agg = (float*)aggPtr;

    int nsm = 148;
    cudaDeviceGetAttribute(&nsm, cudaDevAttrMultiProcessorCount, 0);

    int rpb_sage = (((NN + nsm - 1) / nsm) + 7) & ~7;
    int rpb_dec  = (((2 * PP + nsm - 1) / nsm) + 127) & ~127;

    const int SAGE_SMEM = SAGE_U32 * 4;    // ~105 KB
    const int DEC_SMEM  = DEC_U32 * 4;     // ~212.5 KB
    cudaFuncSetAttribute(sage_half_mma<false, false>,
                         cudaFuncAttributeMaxDynamicSharedMemorySize, SAGE_SMEM);
    cudaFuncSetAttribute(sage_half_mma<true, true>,
                         cudaFuncAttributeMaxDynamicSharedMemorySize, SAGE_SMEM);
    cudaFuncSetAttribute(sage_half_mma<true, false>,
                         cudaFuncAttributeMaxDynamicSharedMemorySize, SAGE_SMEM);
    cudaFuncSetAttribute(decoder_kernel,
                         cudaFuncAttributeMaxDynamicSharedMemorySize, DEC_SMEM);

    static cudaStream_t sB = nullptr;
    static cudaEvent_t evFork = nullptr, evAgg1 = nullptr,
                       evH1 = nullptr, evAgg2 = nullptr;
    if (sB == nullptr) {
        cudaStreamCreateWithFlags(&sB, cudaStreamNonBlocking);
        cudaEventCreateWithFlags(&evFork, cudaEventDisableTiming);
        cudaEventCreateWithFlags(&evAgg1, cudaEventDisableTiming);
        cudaEventCreateWithFlags(&evH1,   cudaEventDisableTiming);
        cudaEventCreateWithFlags(&evAgg2, cudaEventDisableTiming);
    }

    int ablocks = (NN * 32 + 255) / 256;

    // ---- fork ----
    cudaEventRecord(evFork, 0);
    cudaStreamWaitEvent(sB, evFork, 0);

    // streamB: CSR build + aggregate layer 1
    count_kernel<<<(EE + 255) / 256, 256, 0, sB>>>(edst);
    scan_kernel<<<1, 1024, 0, sB>>>();
    fill_kernel<<<(EE + 255) / 256, 256, 0, sB>>>(esrc, edst);
    aggregate_kernel<<<ablocks, 256, 0, sB>>>(x);
    cudaEventRecord(evAgg1, sB);

    // streamA: self half of layer 1 (concurrent with CSR+agg1)
    sage_half_mma<false, false><<<nsm, 512, SAGE_SMEM>>>(x, Ws1, b1, h1,
                                                         rpb_sage);
    cudaStreamWaitEvent(0, evAgg1, 0);
    sage_half_mma<true, true><<<nsm, 512, SAGE_SMEM>>>(agg, Wn1, b1, h1,
                                                       rpb_sage);
    cudaEventRecord(evH1, 0);

    // streamB: aggregate layer 2 (concurrent with sage2_self)
    cudaStreamWaitEvent(sB, evH1, 0);
    aggregate_kernel<<<ablocks, 256, 0, sB>>>(h1);
    cudaEventRecord(evAgg2, sB);

    // streamA: self half of layer 2
    sage_half_mma<false, false><<<nsm, 512, SAGE_SMEM>>>(h1, Ws2, b2, h2,
                                                         rpb_sage);
    cudaStreamWaitEvent(0, evAgg2, 0);
    sage_half_mma<true, false><<<nsm, 512, SAGE_SMEM>>>(agg, Wn2, b2, h2,
                                                        rpb_sage);

    // decoder (128-row double-tile)
    decoder_kernel<<<nsm, 512, DEC_SMEM>>>(h2, ps, pd, ns, nd,
                                           Wd1, bd1, Wd2, bd2, Wd3, bd3, out,
                                           rpb_dec);
}

// round 16
// speedup vs baseline: 1.0983x; 1.0182x over previous
#include <cuda_runtime.h>
#include <cuda_bf16.h>
#include <cstdint>

#define NN 50000
#define EE 600000
#define PP 100000
#define FD 128

// ---- device scratch ----
__device__ float g_agg[NN * FD];
__device__ float g_h1[NN * FD];
__device__ float g_h2[NN * FD];
__device__ int   g_cnt[NN];          // restored to 0 by fill_kernel each run
__device__ int   g_rowstart[NN + 1];
__device__ int   g_csr[EE];

typedef unsigned long long u64;
typedef unsigned int u32;

// bf16 split helpers
__device__ __forceinline__ void bf16_split(float x, unsigned short& h, unsigned short& l) {
    __nv_bfloat16 bh = __float2bfloat16(x);
    float r = x - __bfloat162float(bh);
    __nv_bfloat16 bl = __float2bfloat16(r);
    h = __bfloat16_as_ushort(bh);
    l = __bfloat16_as_ushort(bl);
}
__device__ __forceinline__ u32 pack16(unsigned short lo, unsigned short hi) {
    return (u32)lo | ((u32)hi << 16);
}

// m16n8k16 bf16 MMA, f32 accum
__device__ __forceinline__ void mma16816(float& c0, float& c1, float& c2, float& c3,
                                         u32 a0, u32 a1, u32 a2, u32 a3,
                                         u32 b0, u32 b1) {
    asm volatile(
        "mma.sync.aligned.m16n8k16.row.col.f32.bf16.bf16.f32 "
        "{%0,%1,%2,%3}, {%4,%5,%6,%7}, {%8,%9}, {%0,%1,%2,%3};"
        : "+f"(c0), "+f"(c1), "+f"(c2), "+f"(c3)
        : "r"(a0), "r"(a1), "r"(a2), "r"(a3), "r"(b0), "r"(b1));
}

// ============================================================================
// CSR build (proven)
// ============================================================================
__global__ void count_kernel(const int* __restrict__ dst)
{
    int e = blockIdx.x * blockDim.x + threadIdx.x;
    if (e < EE) atomicAdd(&g_cnt[dst[e]], 1);
}

__global__ void __launch_bounds__(1024, 1) scan_kernel()
{
    __shared__ int wsum[32];
    __shared__ int carry;
    int tid = threadIdx.x, lane = tid & 31, w = tid >> 5;
    if (tid == 0) carry = 0;
    __syncthreads();
    for (int base = 0; base < NN; base += 1024) {
        int i = base + tid;
        int v = (i < NN) ? g_cnt[i] : 0;
        int s = v;
#pragma unroll
        for (int off = 1; off < 32; off <<= 1) {
            int t = __shfl_up_sync(0xffffffffu, s, off);
            if (lane >= off) s += t;
        }
        if (lane == 31) wsum[w] = s;
        __syncthreads();
        if (w == 0) {
            int ws = wsum[lane];
#pragma unroll
            for (int off = 1; off < 32; off <<= 1) {
                int t = __shfl_up_sync(0xffffffffu, ws, off);
                if (lane >= off) ws += t;
            }
            wsum[lane] = ws;
        }
        __syncthreads();
        int prev = (w > 0) ? wsum[w - 1] : 0;
        int incl = carry + prev + s;
        if (i < NN) g_rowstart[i + 1] = incl;
        int chunk_total = wsum[31];
        __syncthreads();
        if (tid == 0) carry += chunk_total;
        __syncthreads();
    }
    if (threadIdx.x == 0) g_rowstart[0] = 0;
}

__global__ void fill_kernel(const int* __restrict__ src,
                            const int* __restrict__ dst)
{
    int e = blockIdx.x * blockDim.x + threadIdx.x;
    if (e >= EE) return;
    int d = dst[e];
    int p = atomicAdd(&g_cnt[d], -1) - 1;
    g_csr[g_rowstart[d] + p] = src[e];
}

// ============================================================================
// Aggregate (proven)
// ============================================================================
__global__ void aggregate_kernel(const float* __restrict__ h)
{
    int gw   = (blockIdx.x * blockDim.x + threadIdx.x) >> 5;
    int lane = threadIdx.x & 31;
    if (gw >= NN) return;
    int beg = g_rowstart[gw], end = g_rowstart[gw + 1];
    const float* hp = h + lane * 4;
    float4 acc = make_float4(0.f, 0.f, 0.f, 0.f);
    int e = beg;
    for (; e + 1 < end; e += 2) {
        int s0 = g_csr[e], s1 = g_csr[e + 1];
        float4 v0 = *(const float4*)(hp + s0 * FD);
        float4 v1 = *(const float4*)(hp + s1 * FD);
        acc.x += v0.x + v1.x; acc.y += v0.y + v1.y;
        acc.z += v0.z + v1.z; acc.w += v0.w + v1.w;
    }
    if (e < end) {
        int s0 = g_csr[e];
        float4 v0 = *(const float4*)(hp + s0 * FD);
        acc.x += v0.x; acc.y += v0.y; acc.z += v0.z; acc.w += v0.w;
    }
    float rd = 1.0f / fmaxf((float)(end - beg), 1.0f);
    acc.x *= rd; acc.y *= rd; acc.z *= rd; acc.w *= rd;
    *(float4*)(g_agg + gw * FD + lane * 4) = acc;
}

// ============================================================================
// Half-K SAGE linear via mma.sync, 128-row DOUBLE-TILE per iteration.
// Two 64-row sub-tiles share weight fragments and barriers.
// ADD=false: out = src @ W + b ; ADD=true: out += src @ W (then opt RELU)
// ============================================================================
#define SPW 136
#define SPZ 68
#define OFF_SWH 0
#define OFF_SWL (OFF_SWH + 64 * SPW)
#define OFF_SZH (OFF_SWL + 64 * SPW)
#define OFF_SZL (OFF_SZH + 128 * SPZ)
#define OFF_SB  (OFF_SZL + 128 * SPZ)
#define SAGE_U32 (OFF_SB + 128)

template <bool ADD, bool RELU>
__global__ void __launch_bounds__(512, 1)
sage_half_mma(const float* __restrict__ src,
              const float* __restrict__ W,
              const float* __restrict__ b,
              float* __restrict__ out,
              int rpb)
{
    extern __shared__ u32 smu[];
    u32* Wh = smu + OFF_SWH;
    u32* Wl = smu + OFF_SWL;
    u32* zh = smu + OFF_SZH;   // [128][SPZ]
    u32* zl = smu + OFF_SZL;   // [128][SPZ]
    float* bs = (float*)(smu + OFF_SB);

    int tid  = threadIdx.x;
    int lane = tid & 31;
    int warp = tid >> 5;
    int g    = lane >> 2;
    int tg   = lane & 3;
    int wr   = warp & 3;
    int wc   = warp >> 2;

    // ---- prologue: weight split ----
    for (int i = tid; i < 64 * 128; i += 512) {
        int t = i >> 7, c = i & 127;
        unsigned short h0, l0, h1, l1;
        bf16_split(W[(2 * t) * 128 + c], h0, l0);
        bf16_split(W[(2 * t + 1) * 128 + c], h1, l1);
        Wh[t * SPW + c] = pack16(h0, h1);
        Wl[t * SPW + c] = pack16(l0, l1);
    }
    if (tid < 128) bs[tid] = b[tid];
    __syncthreads();

    int bstart = blockIdx.x * rpb;
    int bend   = min(bstart + rpb, NN);
    int rb = wr * 16;
    int cb = wc * 32;

    for (int tb = bstart; tb < bend; tb += 128) {

        // ---- stage 128 rows, bf16 split ----
#pragma unroll
        for (int i = 0; i < 8; i++) {
            int rl  = warp * 8 + i;          // 0..127
            int row = tb + rl;
            float4 v = make_float4(0.f, 0.f, 0.f, 0.f);
            if (row < bend)
                v = *(const float4*)(src + row * FD + lane * 4);
            unsigned short h0, l0, h1, l1, h2_, l2_, h3_, l3_;
            bf16_split(v.x, h0, l0); bf16_split(v.y, h1, l1);
            bf16_split(v.z, h2_, l2_); bf16_split(v.w, h3_, l3_);
            u32 base_ = rl * SPZ + 2 * lane;
            *(uint2*)(zh + base_) = make_uint2(pack16(h0, h1), pack16(h2_, h3_));
            *(uint2*)(zl + base_) = make_uint2(pack16(l0, l1), pack16(l2_, l3_));
        }
        __syncthreads();

        float accA[4][4], accB[4][4];
#pragma unroll
        for (int j = 0; j < 4; j++)
#pragma unroll
            for (int q = 0; q < 4; q++) { accA[j][q] = 0.f; accB[j][q] = 0.f; }

#pragma unroll 1
        for (int ks = 0; ks < 8; ks++) {
            int ko = ks * 8;
            int rA0 = (rb + g) * SPZ, rA1 = (rb + 8 + g) * SPZ;
            int rB0 = (64 + rb + g) * SPZ, rB1 = (64 + rb + 8 + g) * SPZ;
            u32 ahA0 = zh[rA0 + ko + tg],     ahA1 = zh[rA1 + ko + tg];
            u32 ahA2 = zh[rA0 + ko + 4 + tg], ahA3 = zh[rA1 + ko + 4 + tg];
            u32 alA0 = zl[rA0 + ko + tg],     alA1 = zl[rA1 + ko + tg];
            u32 alA2 = zl[rA0 + ko + 4 + tg], alA3 = zl[rA1 + ko + 4 + tg];
            u32 ahB0 = zh[rB0 + ko + tg],     ahB1 = zh[rB1 + ko + tg];
            u32 ahB2 = zh[rB0 + ko + 4 + tg], ahB3 = zh[rB1 + ko + 4 + tg];
            u32 alB0 = zl[rB0 + ko + tg],     alB1 = zl[rB1 + ko + tg];
            u32 alB2 = zl[rB0 + ko + 4 + tg], alB3 = zl[rB1 + ko + 4 + tg];
#pragma unroll
            for (int j = 0; j < 4; j++) {
                int c0 = cb + j * 8 + g;
                u32 bh0 = Wh[(ko + tg) * SPW + c0];
                u32 bh1 = Wh[(ko + 4 + tg) * SPW + c0];
                u32 bl0 = Wl[(ko + tg) * SPW + c0];
                u32 bl1 = Wl[(ko + 4 + tg) * SPW + c0];
                mma16816(accA[j][0], accA[j][1], accA[j][2], accA[j][3],
                         ahA0, ahA1, ahA2, ahA3, bh0, bh1);
                mma16816(accB[j][0], accB[j][1], accB[j][2], accB[j][3],
                         ahB0, ahB1, ahB2, ahB3, bh0, bh1);
                mma16816(accA[j][0], accA[j][1], accA[j][2], accA[j][3],
                         ahA0, ahA1, ahA2, ahA3, bl0, bl1);
                mma16816(accB[j][0], accB[j][1], accB[j][2], accB[j][3],
                         ahB0, ahB1, ahB2, ahB3, bl0, bl1);
                mma16816(accA[j][0], accA[j][1], accA[j][2], accA[j][3],
                         alA0, alA1, alA2, alA3, bh0, bh1);
                mma16816(accB[j][0], accB[j][1], accB[j][2], accB[j][3],
                         alB0, alB1, alB2, alB3, bh0, bh1);
            }
        }

        // ---- epilogue: both sub-tiles ----
        {
#pragma unroll
            for (int half = 0; half < 2; half++) {
                int r0 = tb + half * 64 + rb + g;
                int r1 = tb + half * 64 + rb + 8 + g;
#pragma unroll
                for (int j = 0; j < 4; j++) {
                    float a0 = half ? accB[j][0] : accA[j][0];
                    float a1 = half ? accB[j][1] : accA[j][1];
                    float a2 = half ? accB[j][2] : accA[j][2];
                    float a3 = half ? accB[j][3] : accA[j][3];
                    int col0 = cb + j * 8 + 2 * tg;
                    float2 bb = make_float2(0.f, 0.f);
                    if (!ADD) bb = *(float2*)(bs + col0);
                    if (r0 < bend) {
                        float2* op = (float2*)(out + r0 * FD + col0);
                        float2 o;
                        if (ADD) {
                            float2 prev = *op;
                            o.x = a0 + prev.x; o.y = a1 + prev.y;
                        } else {
                            o.x = a0 + bb.x; o.y = a1 + bb.y;
                        }
                        if (RELU) { o.x = fmaxf(o.x, 0.f); o.y = fmaxf(o.y, 0.f); }
                        *op = o;
                    }
                    if (r1 < bend) {
                        float2* op = (float2*)(out + r1 * FD + col0);
                        float2 o;
                        if (ADD) {
                            float2 prev = *op;
                            o.x = a2 + prev.x; o.y = a3 + prev.y;
                        } else {
                            o.x = a2 + bb.x; o.y = a3 + bb.y;
                        }
                        if (RELU) { o.x = fmaxf(o.x, 0.f); o.y = fmaxf(o.y, 0.f); }
                        *op = o;
                    }
                }
            }
        }
        __syncthreads();
    }
}

// ============================================================================
// Decoder via mma.sync, 128-row double-tile (R15 form, FROZEN)
// ============================================================================
#define PW 136
#define PZ 68
#define OFF_W1H 0
#define OFF_W1L (OFF_W1H + 64 * PW)
#define OFF_W2H (OFF_W1L + 64 * PW)
#define OFF_W2L (OFF_W2H + 64 * PW)
#define OFF_ZH  (OFF_W2L + 64 * PW)
#define OFF_ZL  (OFF_ZH + 128 * PZ)
#define OFF_B1  (OFF_ZL + 128 * PZ)
#define OFF_B2  (OFF_B1 + 128)
#define OFF_W3  (OFF_B2 + 128)
#define OFF_RED (OFF_W3 + 128)
#define DEC_U32 (OFF_RED + 128 * 4)

__global__ void __launch_bounds__(512, 1)
decoder_kernel(const float* __restrict__ h,
               const int* __restrict__ ps, const int* __restrict__ pd,
               const int* __restrict__ ns, const int* __restrict__ nd,
               const float* __restrict__ Wd1, const float* __restrict__ bd1,
               const float* __restrict__ Wd2, const float* __restrict__ bd2,
               const float* __restrict__ Wd3, const float* __restrict__ bd3,
               float* __restrict__ out,
               int rpb)
{
    extern __shared__ u32 smu[];
    u32* W1h = smu + OFF_W1H;
    u32* W1l = smu + OFF_W1L;
    u32* W2h = smu + OFF_W2H;
    u32* W2l = smu + OFF_W2L;
    u32* zh  = smu + OFF_ZH;   // [128][PZ]
    u32* zl  = smu + OFF_ZL;   // [128][PZ]
    float* b1s = (float*)(smu + OFF_B1);
    float* b2s = (float*)(smu + OFF_B2);
    float* w3s = (float*)(smu + OFF_W3);
    float* red = (float*)(smu + OFF_RED);   // [128][4]

    int tid  = threadIdx.x;
    int lane = tid & 31;
    int warp = tid >> 5;
    int g    = lane >> 2;
    int tg   = lane & 3;
    int wr   = warp & 3;
    int wc   = warp >> 2;

    for (int i = tid; i < 64 * 128; i += 512) {
        int t = i >> 7, c = i & 127;
        unsigned short h0, l0, h1, l1;
        float a0 = Wd1[(2 * t) * 128 + c], a1 = Wd1[(2 * t + 1) * 128 + c];
        bf16_split(a0, h0, l0); bf16_split(a1, h1, l1);
        W1h[t * PW + c] = pack16(h0, h1);
        W1l[t * PW + c] = pack16(l0, l1);
        float b0f = Wd2[(2 * t) * 128 + c], b1f = Wd2[(2 * t + 1) * 128 + c];
        bf16_split(b0f, h0, l0); bf16_split(b1f, h1, l1);
        W2h[t * PW + c] = pack16(h0, h1);
        W2l[t * PW + c] = pack16(l0, l1);
    }
    if (tid < 128) {
        b1s[tid] = bd1[tid];
        b2s[tid] = bd2[tid];
        w3s[tid] = Wd3[tid];
    }
    __syncthreads();

    const float b3 = bd3[0];
    const int total = 2 * PP;
    int bstart = blockIdx.x * rpb;
    int bend   = min(bstart + rpb, total);
    int rb = wr * 16;
    int cb = wc * 32;

    for (int tb = bstart; tb < bend; tb += 128) {

        // ---- stage 128 pair-rows: z = h[s]*h[d], bf16 split ----
#pragma unroll
        for (int i = 0; i < 8; i++) {
            int rl = warp * 8 + i;          // 0..127
            int p  = tb + rl;
            float4 v = make_float4(0.f, 0.f, 0.f, 0.f);
            if (p < total) {
                int s, d;
                if (p < PP) { s = ps[p]; d = pd[p]; }
                else        { s = ns[p - PP]; d = nd[p - PP]; }
                float4 a = *(const float4*)(h + s * FD + lane * 4);
                float4 c = *(const float4*)(h + d * FD + lane * 4);
                v.x = a.x * c.x; v.y = a.y * c.y;
                v.z = a.z * c.z; v.w = a.w * c.w;
            }
            unsigned short h0, l0, h1, l1, h2_, l2_, h3_, l3_;
            bf16_split(v.x, h0, l0); bf16_split(v.y, h1, l1);
            bf16_split(v.z, h2_, l2_); bf16_split(v.w, h3_, l3_);
            u32 base_ = rl * PZ + 2 * lane;
            *(uint2*)(zh + base_) = make_uint2(pack16(h0, h1), pack16(h2_, h3_));
            *(uint2*)(zl + base_) = make_uint2(pack16(l0, l1), pack16(l2_, l3_));
        }
        __syncthreads();

        float accA[4][4], accB[4][4];

        // ================= GEMV 1 (both sub-tiles) =================
#pragma unroll
        for (int j = 0; j < 4; j++)
#pragma unroll
            for (int q = 0; q < 4; q++) { accA[j][q] = 0.f; accB[j][q] = 0.f; }

#pragma unroll 1
        for (int ks = 0; ks < 8; ks++) {
            int ko = ks * 8;
            int rA0 = (rb + g) * PZ, rA1 = (rb + 8 + g) * PZ;
            int rB0 = (64 + rb + g) * PZ, rB1 = (64 + rb + 8 + g) * PZ;
            u32 ahA0 = zh[rA0 + ko + tg],     ahA1 = zh[rA1 + ko + tg];
            u32 ahA2 = zh[rA0 + ko + 4 + tg], ahA3 = zh[rA1 + ko + 4 + tg];
            u32 alA0 = zl[rA0 + ko + tg],     alA1 = zl[rA1 + ko + tg];
            u32 alA2 = zl[rA0 + ko + 4 + tg], alA3 = zl[rA1 + ko + 4 + tg];
            u32 ahB0 = zh[rB0 + ko + tg],     ahB1 = zh[rB1 + ko + tg];
            u32 ahB2 = zh[rB0 + ko + 4 + tg], ahB3 = zh[rB1 + ko + 4 + tg];
            u32 alB0 = zl[rB0 + ko + tg],     alB1 = zl[rB1 + ko + tg];
            u32 alB2 = zl[rB0 + ko + 4 + tg], alB3 = zl[rB1 + ko + 4 + tg];
#pragma unroll
            for (int j = 0; j < 4; j++) {
                int c0 = cb + j * 8 + g;
                u32 bh0 = W1h[(ko + tg) * PW + c0];
                u32 bh1 = W1h[(ko + 4 + tg) * PW + c0];
                u32 bl0 = W1l[(ko + tg) * PW + c0];
                u32 bl1 = W1l[(ko + 4 + tg) * PW + c0];
                mma16816(accA[j][0], accA[j][1], accA[j][2], accA[j][3],
                         ahA0, ahA1, ahA2, ahA3, bh0, bh1);
                mma16816(accB[j][0], accB[j][1], accB[j][2], accB[j][3],
                         ahB0, ahB1, ahB2, ahB3, bh0, bh1);
                mma16816(accA[j][0], accA[j][1], accA[j][2], accA[j][3],
                         ahA0, ahA1, ahA2, ahA3, bl0, bl1);
                mma16816(accB[j][0], accB[j][1], accB[j][2], accB[j][3],
                         ahB0, ahB1, ahB2, ahB3, bl0, bl1);
                mma16816(accA[j][0], accA[j][1], accA[j][2], accA[j][3],
                         alA0, alA1, alA2, alA3, bh0, bh1);
                mma16816(accB[j][0], accB[j][1], accB[j][2], accB[j][3],
                         alB0, alB1, alB2, alB3, bh0, bh1);
            }
        }
        __syncthreads();

        // ---- t1 = relu(acc + b1), restage both sub-tiles ----
#pragma unroll
        for (int j = 0; j < 4; j++) {
            int col0 = cb + j * 8 + 2 * tg;
            int t2i = col0 >> 1;
            unsigned short h0, l0, h1, l1;
            float t0 = fmaxf(accA[j][0] + b1s[col0],     0.f);
            float t1 = fmaxf(accA[j][1] + b1s[col0 + 1], 0.f);
            bf16_split(t0, h0, l0); bf16_split(t1, h1, l1);
            zh[(rb + g) * PZ + t2i] = pack16(h0, h1);
            zl[(rb + g) * PZ + t2i] = pack16(l0, l1);
            t0 = fmaxf(accA[j][2] + b1s[col0],     0.f);
            t1 = fmaxf(accA[j][3] + b1s[col0 + 1], 0.f);
            bf16_split(t0, h0, l0); bf16_split(t1, h1, l1);
            zh[(rb + 8 + g) * PZ + t2i] = pack16(h0, h1);
            zl[(rb + 8 + g) * PZ + t2i] = pack16(l0, l1);
            t0 = fmaxf(accB[j][0] + b1s[col0],     0.f);
            t1 = fmaxf(accB[j][1] + b1s[col0 + 1], 0.f);
            bf16_split(t0, h0, l0); bf16_split(t1, h1, l1);
            zh[(64 + rb + g) * PZ + t2i] = pack16(h0, h1);
            zl[(64 + rb + g) * PZ + t2i] = pack16(l0, l1);
            t0 = fmaxf(accB[j][2] + b1s[col0],     0.f);
            t1 = fmaxf(accB[j][3] + b1s[col0 + 1], 0.f);
            bf16_split(t0, h0, l0); bf16_split(t1, h1, l1);
            zh[(64 + rb + 8 + g) * PZ + t2i] = pack16(h0, h1);
            zl[(64 + rb + 8 + g) * PZ + t2i] = pack16(l0, l1);
        }
        __syncthreads();

        // ================= GEMV 2 (both sub-tiles) =================
#pragma unroll
        for (int j = 0; j < 4; j++)
#pragma unroll
            for (int q = 0; q < 4; q++) { accA[j][q] = 0.f; accB[j][q] = 0.f; }

#pragma unroll 1
        for (int ks = 0; ks < 8; ks++) {
            int ko = ks * 8;
            int rA0 = (rb + g) * PZ, rA1 = (rb + 8 + g) * PZ;
            int rB0 = (64 + rb + g) * PZ, rB1 = (64 + rb + 8 + g) * PZ;
            u32 ahA0 = zh[rA0 + ko + tg],     ahA1 = zh[rA1 + ko + tg];
            u32 ahA2 = zh[rA0 + ko + 4 + tg], ahA3 = zh[rA1 + ko + 4 + tg];
            u32 alA0 = zl[rA0 + ko + tg],     alA1 = zl[rA1 + ko + tg];
            u32 alA2 = zl[rA0 + ko + 4 + tg], alA3 = zl[rA1 + ko + 4 + tg];
            u32 ahB0 = zh[rB0 + ko + tg],     ahB1 = zh[rB1 + ko + tg];
            u32 ahB2 = zh[rB0 + ko + 4 + tg], ahB3 = zh[rB1 + ko + 4 + tg];
            u32 alB0 = zl[rB0 + ko + tg],     alB1 = zl[rB1 + ko + tg];
            u32 alB2 = zl[rB0 + ko + 4 + tg], alB3 = zl[rB1 + ko + 4 + tg];
#pragma unroll
            for (int j = 0; j < 4; j++) {
                int c0 = cb + j * 8 + g;
                u32 bh0 = W2h[(ko + tg) * PW + c0];
                u32 bh1 = W2h[(ko + 4 + tg) * PW + c0];
                u32 bl0 = W2l[(ko + tg) * PW + c0];
                u32 bl1 = W2l[(ko + 4 + tg) * PW + c0];
                mma16816(accA[j][0], accA[j][1], accA[j][2], accA[j][3],
                         ahA0, ahA1, ahA2, ahA3, bh0, bh1);
                mma16816(accB[j][0], accB[j][1], accB[j][2], accB[j][3],
                         ahB0, ahB1, ahB2, ahB3, bh0, bh1);
                mma16816(accA[j][0], accA[j][1], accA[j][2], accA[j][3],
                         ahA0, ahA1, ahA2, ahA3, bl0, bl1);
                mma16816(accB[j][0], accB[j][1], accB[j][2], accB[j][3],
                         ahB0, ahB1, ahB2, ahB3, bl0, bl1);
                mma16816(accA[j][0], accA[j][1], accA[j][2], accA[j][3],
                         alA0, alA1, alA2, alA3, bh0, bh1);
                mma16816(accB[j][0], accB[j][1], accB[j][2], accB[j][3],
                         alB0, alB1, alB2, alB3, bh0, bh1);
            }
        }

        // ---- out = relu(acc + b2) . Wd3 + bd3 (both sub-tiles) ----
        {
            float pA0 = 0.f, pA1 = 0.f, pB0 = 0.f, pB1 = 0.f;
#pragma unroll
            for (int j = 0; j < 4; j++) {
                int col0 = cb + j * 8 + 2 * tg;
                float wa = w3s[col0], wb = w3s[col0 + 1];
                pA0 += fmaxf(accA[j][0] + b2s[col0],     0.f) * wa
                     + fmaxf(accA[j][1] + b2s[col0 + 1], 0.f) * wb;
                pA1 += fmaxf(accA[j][2] + b2s[col0],     0.f) * wa
                     + fmaxf(accA[j][3] + b2s[col0 + 1], 0.f) * wb;
                pB0 += fmaxf(accB[j][0] + b2s[col0],     0.f) * wa
                     + fmaxf(accB[j][1] + b2s[col0 + 1], 0.f) * wb;
                pB1 += fmaxf(accB[j][2] + b2s[col0],     0.f) * wa
                     + fmaxf(accB[j][3] + b2s[col0 + 1], 0.f) * wb;
            }
            pA0 += __shfl_xor_sync(0xffffffffu, pA0, 1);
            pA0 += __shfl_xor_sync(0xffffffffu, pA0, 2);
            pA1 += __shfl_xor_sync(0xffffffffu, pA1, 1);
            pA1 += __shfl_xor_sync(0xffffffffu, pA1, 2);
            pB0 += __shfl_xor_sync(0xffffffffu, pB0, 1);
            pB0 += __shfl_xor_sync(0xffffffffu, pB0, 2);
            pB1 += __shfl_xor_sync(0xffffffffu, pB1, 1);
            pB1 += __shfl_xor_sync(0xffffffffu, pB1, 2);
            if (tg == 0) {
                red[(rb + g) * 4 + wc]          = pA0;
                red[(rb + 8 + g) * 4 + wc]      = pA1;
                red[(64 + rb + g) * 4 + wc]     = pB0;
                red[(64 + rb + 8 + g) * 4 + wc] = pB1;
            }
        }
        __syncthreads();

        if (tid < 128) {
            int p = tb + tid;
            if (p < total)
                out[p] = red[tid * 4] + red[tid * 4 + 1]
                       + red[tid * 4 + 2] + red[tid * 4 + 3] + b3;
        }
        __syncthreads();
    }
}

// ============================================================================
// launch — two-stream fork/join
// ============================================================================
extern "C" void kernel_launch(void* const* d_in, const int* in_sizes, int n_in,
                              void* d_out, int out_size)
{
    const float* x    = (const float*)d_in[0];
    const int*   esrc = (const int*)  d_in[1];
    const int*   edst = (const int*)  d_in[2];
    const int*   ps   = (const int*)  d_in[3];
    const int*   pd   = (const int*)  d_in[4];
    const int*   ns   = (const int*)  d_in[5];
    const int*   nd   = (const int*)  d_in[6];
    const float* Ws1  = (const float*)d_in[7];
    const float* Wn1  = (const float*)d_in[8];
    const float* b1   = (const float*)d_in[9];
    const float* Ws2  = (const float*)d_in[10];
    const float* Wn2  = (const float*)d_in[11];
    const float* b2   = (const float*)d_in[12];
    const float* Wd1  = (const float*)d_in[13];
    const float* bd1  = (const float*)d_in[14];
    const float* Wd2  = (const float*)d_in[15];
    const float* bd2  = (const float*)d_in[16];
    const float* Wd3  = (const float*)d_in[17];
    const float* bd3  = (const float*)d_in[18];
    float* out = (float*)d_out;

    void *aggPtr, *h1Ptr, *h2Ptr;
    cudaGetSymbolAddress(&aggPtr, g_agg);
    cudaGetSymbolAddress(&h1Ptr,  g_h1);
    cudaGetSymbolAddress(&h2Ptr,  g_h2);
    float* h1 = (float*)h1Ptr;
    float* h2 = (float*)h2Ptr;
    float* agg = (float*)aggPtr;

    int nsm = 148;
    cudaDeviceGetAttribute(&nsm, cudaDevAttrMultiProcessorCount, 0);

    int rpb_sage = (((NN + nsm - 1) / nsm) + 127) & ~127;
    int rpb_dec  = (((2 * PP + nsm - 1) / nsm) + 127) & ~127;

    const int SAGE_SMEM = SAGE_U32 * 4;    // ~140 KB
    const int DEC_SMEM  = DEC_U32 * 4;     // ~212.5 KB
    cudaFuncSetAttribute(sage_half_mma<false, false>,
                         cudaFuncAttributeMaxDynamicSharedMemorySize, SAGE_SMEM);
    cudaFuncSetAttribute(sage_half_mma<true, true>,
                         cudaFuncAttributeMaxDynamicSharedMemorySize, SAGE_SMEM);
    cudaFuncSetAttribute(sage_half_mma<true, false>,
                         cudaFuncAttributeMaxDynamicSharedMemorySize, SAGE_SMEM);
    cudaFuncSetAttribute(decoder_kernel,
                         cudaFuncAttributeMaxDynamicSharedMemorySize, DEC_SMEM);

    static cudaStream_t sB = nullptr;
    static cudaEvent_t evFork = nullptr, evAgg1 = nullptr,
                       evH1 = nullptr, evAgg2 = nullptr;
    if (sB == nullptr) {
        cudaStreamCreateWithFlags(&sB, cudaStreamNonBlocking);
        cudaEventCreateWithFlags(&evFork, cudaEventDisableTiming);
        cudaEventCreateWithFlags(&evAgg1, cudaEventDisableTiming);
        cudaEventCreateWithFlags(&evH1,   cudaEventDisableTiming);
        cudaEventCreateWithFlags(&evAgg2, cudaEventDisableTiming);
    }

    int ablocks = (NN * 32 + 255) / 256;

    // ---- fork ----
    cudaEventRecord(evFork, 0);
    cudaStreamWaitEvent(sB, evFork, 0);

    // streamB: CSR build + aggregate layer 1
    count_kernel<<<(EE + 255) / 256, 256, 0, sB>>>(edst);
    scan_kernel<<<1, 1024, 0, sB>>>();
    fill_kernel<<<(EE + 255) / 256, 256, 0, sB>>>(esrc, edst);
    aggregate_kernel<<<ablocks, 256, 0, sB>>>(x);
    cudaEventRecord(evAgg1, sB);

    // streamA: self half of layer 1 (concurrent with CSR+agg1)
    sage_half_mma<false, false><<<nsm, 512, SAGE_SMEM>>>(x, Ws1, b1, h1,
                                                         rpb_sage);
    cudaStreamWaitEvent(0, evAgg1, 0);
    sage_half_mma<true, true><<<nsm, 512, SAGE_SMEM>>>(agg, Wn1, b1, h1,
                                                       rpb_sage);
    cudaEventRecord(evH1, 0);

    // streamB: aggregate layer 2 (concurrent with sage2_self)
    cudaStreamWaitEvent(sB, evH1, 0);
    aggregate_kernel<<<ablocks, 256, 0, sB>>>(h1);
    cudaEventRecord(evAgg2, sB);

    // streamA: self half of layer 2
    sage_half_mma<false, false><<<nsm, 512, SAGE_SMEM>>>(h1, Ws2, b2, h2,
                                                         rpb_sage);
    cudaStreamWaitEvent(0, evAgg2, 0);
    sage_half_mma<true, false><<<nsm, 512, SAGE_SMEM>>>(agg, Wn2, b2, h2,
                                                        rpb_sage);

    // decoder (128-row double-tile)
    decoder_kernel<<<nsm, 512, DEC_SMEM>>>(h2, ps, pd, ns, nd,
                                           Wd1, bd1, Wd2, bd2, Wd3, bd3, out,
                                           rpb_dec);
}

// round 17
// speedup vs baseline: 1.1166x; 1.0166x over previous
#include <cuda_runtime.h>
#include <cuda_bf16.h>
#include <cstdint>

#define NN 50000
#define EE 600000
#define PP 100000
#define FD 128

// ---- device scratch ----
__device__ float g_agg[NN * FD];
__device__ float g_h1[NN * FD];
__device__ float g_h2[NN * FD];
__device__ int   g_cnt[NN];          // restored to 0 by fill_kernel each run
__device__ int   g_rowstart[NN + 1];
__device__ int   g_csr[EE];

typedef unsigned long long u64;
typedef unsigned int u32;

// pre-split weights: [matrix 0..5][entry t*128+c], matrices:
// 0=Ws1 1=Wn1 2=Ws2 3=Wn2 4=Wd1 5=Wd2
__device__ u32 g_Wh[6][64 * 128];
__device__ u32 g_Wl[6][64 * 128];

// bf16 split helpers
__device__ __forceinline__ void bf16_split(float x, unsigned short& h, unsigned short& l) {
    __nv_bfloat16 bh = __float2bfloat16(x);
    float r = x - __bfloat162float(bh);
    __nv_bfloat16 bl = __float2bfloat16(r);
    h = __bfloat16_as_ushort(bh);
    l = __bfloat16_as_ushort(bl);
}
__device__ __forceinline__ u32 pack16(unsigned short lo, unsigned short hi) {
    return (u32)lo | ((u32)hi << 16);
}

// m16n8k16 bf16 MMA, f32 accum
__device__ __forceinline__ void mma16816(float& c0, float& c1, float& c2, float& c3,
                                         u32 a0, u32 a1, u32 a2, u32 a3,
                                         u32 b0, u32 b1) {
    asm volatile(
        "mma.sync.aligned.m16n8k16.row.col.f32.bf16.bf16.f32 "
        "{%0,%1,%2,%3}, {%4,%5,%6,%7}, {%8,%9}, {%0,%1,%2,%3};"
        : "+f"(c0), "+f"(c1), "+f"(c2), "+f"(c3)
        : "r"(a0), "r"(a1), "r"(a2), "r"(a3), "r"(b0), "r"(b1));
}

// ============================================================================
// One-time weight pre-split (runs once per launch, hidden on streamB)
// ============================================================================
__global__ void split_weights_kernel(const float* __restrict__ Ws1,
                                     const float* __restrict__ Wn1,
                                     const float* __restrict__ Ws2,
                                     const float* __restrict__ Wn2,
                                     const float* __restrict__ Wd1,
                                     const float* __restrict__ Wd2)
{
    int i = blockIdx.x * blockDim.x + threadIdx.x;
    if (i >= 6 * 8192) return;
    int m = i >> 13, e = i & 8191;
    const float* W = (m == 0) ? Ws1 : (m == 1) ? Wn1 : (m == 2) ? Ws2
                   : (m == 3) ? Wn2 : (m == 4) ? Wd1 : Wd2;
    int t = e >> 7, c = e & 127;
    unsigned short h0, l0, h1, l1;
    bf16_split(W[(2 * t) * 128 + c], h0, l0);
    bf16_split(W[(2 * t + 1) * 128 + c], h1, l1);
    g_Wh[m][e] = pack16(h0, h1);
    g_Wl[m][e] = pack16(l0, l1);
}

// ============================================================================
// CSR build (proven)
// ============================================================================
__global__ void count_kernel(const int* __restrict__ dst)
{
    int e = blockIdx.x * blockDim.x + threadIdx.x;
    if (e < EE) atomicAdd(&g_cnt[dst[e]], 1);
}

__global__ void __launch_bounds__(1024, 1) scan_kernel()
{
    __shared__ int wsum[32];
    __shared__ int carry;
    int tid = threadIdx.x, lane = tid & 31, w = tid >> 5;
    if (tid == 0) carry = 0;
    __syncthreads();
    for (int base = 0; base < NN; base += 1024) {
        int i = base + tid;
        int v = (i < NN) ? g_cnt[i] : 0;
        int s = v;
#pragma unroll
        for (int off = 1; off < 32; off <<= 1) {
            int t = __shfl_up_sync(0xffffffffu, s, off);
            if (lane >= off) s += t;
        }
        if (lane == 31) wsum[w] = s;
        __syncthreads();
        if (w == 0) {
            int ws = wsum[lane];
#pragma unroll
            for (int off = 1; off < 32; off <<= 1) {
                int t = __shfl_up_sync(0xffffffffu, ws, off);
                if (lane >= off) ws += t;
            }
            wsum[lane] = ws;
        }
        __syncthreads();
        int prev = (w > 0) ? wsum[w - 1] : 0;
        int incl = carry + prev + s;
        if (i < NN) g_rowstart[i + 1] = incl;
        int chunk_total = wsum[31];
        __syncthreads();
        if (tid == 0) carry += chunk_total;
        __syncthreads();
    }
    if (threadIdx.x == 0) g_rowstart[0] = 0;
}

__global__ void fill_kernel(const int* __restrict__ src,
                            const int* __restrict__ dst)
{
    int e = blockIdx.x * blockDim.x + threadIdx.x;
    if (e >= EE) return;
    int d = dst[e];
    int p = atomicAdd(&g_cnt[d], -1) - 1;
    g_csr[g_rowstart[d] + p] = src[e];
}

// ============================================================================
// Aggregate (proven)
// ============================================================================
__global__ void aggregate_kernel(const float* __restrict__ h)
{
    int gw   = (blockIdx.x * blockDim.x + threadIdx.x) >> 5;
    int lane = threadIdx.x & 31;
    if (gw >= NN) return;
    int beg = g_rowstart[gw], end = g_rowstart[gw + 1];
    const float* hp = h + lane * 4;
    float4 acc = make_float4(0.f, 0.f, 0.f, 0.f);
    int e = beg;
    for (; e + 1 < end; e += 2) {
        int s0 = g_csr[e], s1 = g_csr[e + 1];
        float4 v0 = *(const float4*)(hp + s0 * FD);
        float4 v1 = *(const float4*)(hp + s1 * FD);
        acc.x += v0.x + v1.x; acc.y += v0.y + v1.y;
        acc.z += v0.z + v1.z; acc.w += v0.w + v1.w;
    }
    if (e < end) {
        int s0 = g_csr[e];
        float4 v0 = *(const float4*)(hp + s0 * FD);
        acc.x += v0.x; acc.y += v0.y; acc.z += v0.z; acc.w += v0.w;
    }
    float rd = 1.0f / fmaxf((float)(end - beg), 1.0f);
    acc.x *= rd; acc.y *= rd; acc.z *= rd; acc.w *= rd;
    *(float4*)(g_agg + gw * FD + lane * 4) = acc;
}

// ============================================================================
// Half-K SAGE linear via mma.sync, 128-row DOUBLE-TILE (R16 form);
// prologue now copies pre-split weights.
// ============================================================================
#define SPW 136
#define SPZ 68
#define OFF_SWH 0
#define OFF_SWL (OFF_SWH + 64 * SPW)
#define OFF_SZH (OFF_SWL + 64 * SPW)
#define OFF_SZL (OFF_SZH + 128 * SPZ)
#define OFF_SB  (OFF_SZL + 128 * SPZ)
#define SAGE_U32 (OFF_SB + 128)

template <bool ADD, bool RELU>
__global__ void __launch_bounds__(512, 1)
sage_half_mma(const float* __restrict__ src,
              const u32* __restrict__ Wph,
              const u32* __restrict__ Wpl,
              const float* __restrict__ b,
              float* __restrict__ out,
              int rpb)
{
    extern __shared__ u32 smu[];
    u32* Wh = smu + OFF_SWH;
    u32* Wl = smu + OFF_SWL;
    u32* zh = smu + OFF_SZH;   // [128][SPZ]
    u32* zl = smu + OFF_SZL;   // [128][SPZ]
    float* bs = (float*)(smu + OFF_SB);

    int tid  = threadIdx.x;
    int lane = tid & 31;
    int warp = tid >> 5;
    int g    = lane >> 2;
    int tg   = lane & 3;
    int wr   = warp & 3;
    int wc   = warp >> 2;

    // ---- prologue: copy pre-split weights ----
    for (int i = tid; i < 8192; i += 512) {
        int t = i >> 7, c = i & 127;
        Wh[t * SPW + c] = Wph[i];
        Wl[t * SPW + c] = Wpl[i];
    }
    if (tid < 128) bs[tid] = b[tid];
    __syncthreads();

    int bstart = blockIdx.x * rpb;
    int bend   = min(bstart + rpb, NN);
    int rb = wr * 16;
    int cb = wc * 32;

    for (int tb = bstart; tb < bend; tb += 128) {

        // ---- stage 128 rows, bf16 split ----
#pragma unroll
        for (int i = 0; i < 8; i++) {
            int rl  = warp * 8 + i;          // 0..127
            int row = tb + rl;
            float4 v = make_float4(0.f, 0.f, 0.f, 0.f);
            if (row < bend)
                v = *(const float4*)(src + row * FD + lane * 4);
            unsigned short h0, l0, h1, l1, h2_, l2_, h3_, l3_;
            bf16_split(v.x, h0, l0); bf16_split(v.y, h1, l1);
            bf16_split(v.z, h2_, l2_); bf16_split(v.w, h3_, l3_);
            u32 base_ = rl * SPZ + 2 * lane;
            *(uint2*)(zh + base_) = make_uint2(pack16(h0, h1), pack16(h2_, h3_));
            *(uint2*)(zl + base_) = make_uint2(pack16(l0, l1), pack16(l2_, l3_));
        }
        __syncthreads();

        float accA[4][4], accB[4][4];
#pragma unroll
        for (int j = 0; j < 4; j++)
#pragma unroll
            for (int q = 0; q < 4; q++) { accA[j][q] = 0.f; accB[j][q] = 0.f; }

#pragma unroll 1
        for (int ks = 0; ks < 8; ks++) {
            int ko = ks * 8;
            int rA0 = (rb + g) * SPZ, rA1 = (rb + 8 + g) * SPZ;
            int rB0 = (64 + rb + g) * SPZ, rB1 = (64 + rb + 8 + g) * SPZ;
            u32 ahA0 = zh[rA0 + ko + tg],     ahA1 = zh[rA1 + ko + tg];
            u32 ahA2 = zh[rA0 + ko + 4 + tg], ahA3 = zh[rA1 + ko + 4 + tg];
            u32 alA0 = zl[rA0 + ko + tg],     alA1 = zl[rA1 + ko + tg];
            u32 alA2 = zl[rA0 + ko + 4 + tg], alA3 = zl[rA1 + ko + 4 + tg];
            u32 ahB0 = zh[rB0 + ko + tg],     ahB1 = zh[rB1 + ko + tg];
            u32 ahB2 = zh[rB0 + ko + 4 + tg], ahB3 = zh[rB1 + ko + 4 + tg];
            u32 alB0 = zl[rB0 + ko + tg],     alB1 = zl[rB1 + ko + tg];
            u32 alB2 = zl[rB0 + ko + 4 + tg], alB3 = zl[rB1 + ko + 4 + tg];
#pragma unroll
            for (int j = 0; j < 4; j++) {
                int c0 = cb + j * 8 + g;
                u32 bh0 = Wh[(ko + tg) * SPW + c0];
                u32 bh1 = Wh[(ko + 4 + tg) * SPW + c0];
                u32 bl0 = Wl[(ko + tg) * SPW + c0];
                u32 bl1 = Wl[(ko + 4 + tg) * SPW + c0];
                mma16816(accA[j][0], accA[j][1], accA[j][2], accA[j][3],
                         ahA0, ahA1, ahA2, ahA3, bh0, bh1);
                mma16816(accB[j][0], accB[j][1], accB[j][2], accB[j][3],
                         ahB0, ahB1, ahB2, ahB3, bh0, bh1);
                mma16816(accA[j][0], accA[j][1], accA[j][2], accA[j][3],
                         ahA0, ahA1, ahA2, ahA3, bl0, bl1);
                mma16816(accB[j][0], accB[j][1], accB[j][2], accB[j][3],
                         ahB0, ahB1, ahB2, ahB3, bl0, bl1);
                mma16816(accA[j][0], accA[j][1], accA[j][2], accA[j][3],
                         alA0, alA1, alA2, alA3, bh0, bh1);
                mma16816(accB[j][0], accB[j][1], accB[j][2], accB[j][3],
                         alB0, alB1, alB2, alB3, bh0, bh1);
            }
        }

        // ---- epilogue: both sub-tiles ----
        {
#pragma unroll
            for (int half = 0; half < 2; half++) {
                int r0 = tb + half * 64 + rb + g;
                int r1 = tb + half * 64 + rb + 8 + g;
#pragma unroll
                for (int j = 0; j < 4; j++) {
                    float a0 = half ? accB[j][0] : accA[j][0];
                    float a1 = half ? accB[j][1] : accA[j][1];
                    float a2 = half ? accB[j][2] : accA[j][2];
                    float a3 = half ? accB[j][3] : accA[j][3];
                    int col0 = cb + j * 8 + 2 * tg;
                    float2 bb = make_float2(0.f, 0.f);
                    if (!ADD) bb = *(float2*)(bs + col0);
                    if (r0 < bend) {
                        float2* op = (float2*)(out + r0 * FD + col0);
                        float2 o;
                        if (ADD) {
                            float2 prev = *op;
                            o.x = a0 + prev.x; o.y = a1 + prev.y;
                        } else {
                            o.x = a0 + bb.x; o.y = a1 + bb.y;
                        }
                        if (RELU) { o.x = fmaxf(o.x, 0.f); o.y = fmaxf(o.y, 0.f); }
                        *op = o;
                    }
                    if (r1 < bend) {
                        float2* op = (float2*)(out + r1 * FD + col0);
                        float2 o;
                        if (ADD) {
                            float2 prev = *op;
                            o.x = a2 + prev.x; o.y = a3 + prev.y;
                        } else {
                            o.x = a2 + bb.x; o.y = a3 + bb.y;
                        }
                        if (RELU) { o.x = fmaxf(o.x, 0.f); o.y = fmaxf(o.y, 0.f); }
                        *op = o;
                    }
                }
            }
        }
        __syncthreads();
    }
}

// ============================================================================
// Decoder via mma.sync, 128-row double-tile (R16 form); pre-split weights.
// ============================================================================
#define PW 136
#define PZ 68
#define OFF_W1H 0
#define OFF_W1L (OFF_W1H + 64 * PW)
#define OFF_W2H (OFF_W1L + 64 * PW)
#define OFF_W2L (OFF_W2H + 64 * PW)
#define OFF_ZH  (OFF_W2L + 64 * PW)
#define OFF_ZL  (OFF_ZH + 128 * PZ)
#define OFF_B1  (OFF_ZL + 128 * PZ)
#define OFF_B2  (OFF_B1 + 128)
#define OFF_W3  (OFF_B2 + 128)
#define OFF_RED (OFF_W3 + 128)
#define DEC_U32 (OFF_RED + 128 * 4)

__global__ void __launch_bounds__(512, 1)
decoder_kernel(const float* __restrict__ h,
               const int* __restrict__ ps, const int* __restrict__ pd,
               const int* __restrict__ ns, const int* __restrict__ nd,
               const u32* __restrict__ W1ph, const u32* __restrict__ W1pl,
               const u32* __restrict__ W2ph, const u32* __restrict__ W2pl,
               const float* __restrict__ bd1,
               const float* __restrict__ bd2,
               const float* __restrict__ Wd3, const float* __restrict__ bd3,
               float* __restrict__ out,
               int rpb)
{
    extern __shared__ u32 smu[];
    u32* W1h = smu + OFF_W1H;
    u32* W1l = smu + OFF_W1L;
    u32* W2h = smu + OFF_W2H;
    u32* W2l = smu + OFF_W2L;
    u32* zh  = smu + OFF_ZH;   // [128][PZ]
    u32* zl  = smu + OFF_ZL;   // [128][PZ]
    float* b1s = (float*)(smu + OFF_B1);
    float* b2s = (float*)(smu + OFF_B2);
    float* w3s = (float*)(smu + OFF_W3);
    float* red = (float*)(smu + OFF_RED);   // [128][4]

    int tid  = threadIdx.x;
    int lane = tid & 31;
    int warp = tid >> 5;
    int g    = lane >> 2;
    int tg   = lane & 3;
    int wr   = warp & 3;
    int wc   = warp >> 2;

    for (int i = tid; i < 8192; i += 512) {
        int t = i >> 7, c = i & 127;
        W1h[t * PW + c] = W1ph[i];
        W1l[t * PW + c] = W1pl[i];
        W2h[t * PW + c] = W2ph[i];
        W2l[t * PW + c] = W2pl[i];
    }
    if (tid < 128) {
        b1s[tid] = bd1[tid];
        b2s[tid] = bd2[tid];
        w3s[tid] = Wd3[tid];
    }
    __syncthreads();

    const float b3 = bd3[0];
    const int total = 2 * PP;
    int bstart = blockIdx.x * rpb;
    int bend   = min(bstart + rpb, total);
    int rb = wr * 16;
    int cb = wc * 32;

    for (int tb = bstart; tb < bend; tb += 128) {

        // ---- stage 128 pair-rows: z = h[s]*h[d], bf16 split ----
#pragma unroll
        for (int i = 0; i < 8; i++) {
            int rl = warp * 8 + i;          // 0..127
            int p  = tb + rl;
            float4 v = make_float4(0.f, 0.f, 0.f, 0.f);
            if (p < total) {
                int s, d;
                if (p < PP) { s = ps[p]; d = pd[p]; }
                else        { s = ns[p - PP]; d = nd[p - PP]; }
                float4 a = *(const float4*)(h + s * FD + lane * 4);
                float4 c = *(const float4*)(h + d * FD + lane * 4);
                v.x = a.x * c.x; v.y = a.y * c.y;
                v.z = a.z * c.z; v.w = a.w * c.w;
            }
            unsigned short h0, l0, h1, l1, h2_, l2_, h3_, l3_;
            bf16_split(v.x, h0, l0); bf16_split(v.y, h1, l1);
            bf16_split(v.z, h2_, l2_); bf16_split(v.w, h3_, l3_);
            u32 base_ = rl * PZ + 2 * lane;
            *(uint2*)(zh + base_) = make_uint2(pack16(h0, h1), pack16(h2_, h3_));
            *(uint2*)(zl + base_) = make_uint2(pack16(l0, l1), pack16(l2_, l3_));
        }
        __syncthreads();

        float accA[4][4], accB[4][4];

        // ================= GEMV 1 (both sub-tiles) =================
#pragma unroll
        for (int j = 0; j < 4; j++)
#pragma unroll
            for (int q = 0; q < 4; q++) { accA[j][q] = 0.f; accB[j][q] = 0.f; }

#pragma unroll 1
        for (int ks = 0; ks < 8; ks++) {
            int ko = ks * 8;
            int rA0 = (rb + g) * PZ, rA1 = (rb + 8 + g) * PZ;
            int rB0 = (64 + rb + g) * PZ, rB1 = (64 + rb + 8 + g) * PZ;
            u32 ahA0 = zh[rA0 + ko + tg],     ahA1 = zh[rA1 + ko + tg];
            u32 ahA2 = zh[rA0 + ko + 4 + tg], ahA3 = zh[rA1 + ko + 4 + tg];
            u32 alA0 = zl[rA0 + ko + tg],     alA1 = zl[rA1 + ko + tg];
            u32 alA2 = zl[rA0 + ko + 4 + tg], alA3 = zl[rA1 + ko + 4 + tg];
            u32 ahB0 = zh[rB0 + ko + tg],     ahB1 = zh[rB1 + ko + tg];
            u32 ahB2 = zh[rB0 + ko + 4 + tg], ahB3 = zh[rB1 + ko + 4 + tg];
            u32 alB0 = zl[rB0 + ko + tg],     alB1 = zl[rB1 + ko + tg];
            u32 alB2 = zl[rB0 + ko + 4 + tg], alB3 = zl[rB1 + ko + 4 + tg];
#pragma unroll
            for (int j = 0; j < 4; j++) {
                int c0 = cb + j * 8 + g;
                u32 bh0 = W1h[(ko + tg) * PW + c0];
                u32 bh1 = W1h[(ko + 4 + tg) * PW + c0];
                u32 bl0 = W1l[(ko + tg) * PW + c0];
                u32 bl1 = W1l[(ko + 4 + tg) * PW + c0];
                mma16816(accA[j][0], accA[j][1], accA[j][2], accA[j][3],
                         ahA0, ahA1, ahA2, ahA3, bh0, bh1);
                mma16816(accB[j][0], accB[j][1], accB[j][2], accB[j][3],
                         ahB0, ahB1, ahB2, ahB3, bh0, bh1);
                mma16816(accA[j][0], accA[j][1], accA[j][2], accA[j][3],
                         ahA0, ahA1, ahA2, ahA3, bl0, bl1);
                mma16816(accB[j][0], accB[j][1], accB[j][2], accB[j][3],
                         ahB0, ahB1, ahB2, ahB3, bl0, bl1);
                mma16816(accA[j][0], accA[j][1], accA[j][2], accA[j][3],
                         alA0, alA1, alA2, alA3, bh0, bh1);
                mma16816(accB[j][0], accB[j][1], accB[j][2], accB[j][3],
                         alB0, alB1, alB2, alB3, bh0, bh1);
            }
        }
        __syncthreads();

        // ---- t1 = relu(acc + b1), restage both sub-tiles ----
#pragma unroll
        for (int j = 0; j < 4; j++) {
            int col0 = cb + j * 8 + 2 * tg;
            int t2i = col0 >> 1;
            unsigned short h0, l0, h1, l1;
            float t0 = fmaxf(accA[j][0] + b1s[col0],     0.f);
            float t1 = fmaxf(accA[j][1] + b1s[col0 + 1], 0.f);
            bf16_split(t0, h0, l0); bf16_split(t1, h1, l1);
            zh[(rb + g) * PZ + t2i] = pack16(h0, h1);
            zl[(rb + g) * PZ + t2i] = pack16(l0, l1);
            t0 = fmaxf(accA[j][2] + b1s[col0],     0.f);
            t1 = fmaxf(accA[j][3] + b1s[col0 + 1], 0.f);
            bf16_split(t0, h0, l0); bf16_split(t1, h1, l1);
            zh[(rb + 8 + g) * PZ + t2i] = pack16(h0, h1);
            zl[(rb + 8 + g) * PZ + t2i] = pack16(l0, l1);
            t0 = fmaxf(accB[j][0] + b1s[col0],     0.f);
            t1 = fmaxf(accB[j][1] + b1s[col0 + 1], 0.f);
            bf16_split(t0, h0, l0); bf16_split(t1, h1, l1);
            zh[(64 + rb + g) * PZ + t2i] = pack16(h0, h1);
            zl[(64 + rb + g) * PZ + t2i] = pack16(l0, l1);
            t0 = fmaxf(accB[j][2] + b1s[col0],     0.f);
            t1 = fmaxf(accB[j][3] + b1s[col0 + 1], 0.f);
            bf16_split(t0, h0, l0); bf16_split(t1, h1, l1);
            zh[(64 + rb + 8 + g) * PZ + t2i] = pack16(h0, h1);
            zl[(64 + rb + 8 + g) * PZ + t2i] = pack16(l0, l1);
        }
        __syncthreads();

        // ================= GEMV 2 (both sub-tiles) =================
#pragma unroll
        for (int j = 0; j < 4; j++)
#pragma unroll
            for (int q = 0; q < 4; q++) { accA[j][q] = 0.f; accB[j][q] = 0.f; }

#pragma unroll 1
        for (int ks = 0; ks < 8; ks++) {
            int ko = ks * 8;
            int rA0 = (rb + g) * PZ, rA1 = (rb + 8 + g) * PZ;
            int rB0 = (64 + rb + g) * PZ, rB1 = (64 + rb + 8 + g) * PZ;
            u32 ahA0 = zh[rA0 + ko + tg],     ahA1 = zh[rA1 + ko + tg];
            u32 ahA2 = zh[rA0 + ko + 4 + tg], ahA3 = zh[rA1 + ko + 4 + tg];
            u32 alA0 = zl[rA0 + ko + tg],     alA1 = zl[rA1 + ko + tg];
            u32 alA2 = zl[rA0 + ko + 4 + tg], alA3 = zl[rA1 + ko + 4 + tg];
            u32 ahB0 = zh[rB0 + ko + tg],     ahB1 = zh[rB1 + ko + tg];
            u32 ahB2 = zh[rB0 + ko + 4 + tg], ahB3 = zh[rB1 + ko + 4 + tg];
            u32 alB0 = zl[rB0 + ko + tg],     alB1 = zl[rB1 + ko + tg];
            u32 alB2 = zl[rB0 + ko + 4 + tg], alB3 = zl[rB1 + ko + 4 + tg];
#pragma unroll
            for (int j = 0; j < 4; j++) {
                int c0 = cb + j * 8 + g;
                u32 bh0 = W2h[(ko + tg) * PW + c0];
                u32 bh1 = W2h[(ko + 4 + tg) * PW + c0];
                u32 bl0 = W2l[(ko + tg) * PW + c0];
                u32 bl1 = W2l[(ko + 4 + tg) * PW + c0];
                mma16816(accA[j][0], accA[j][1], accA[j][2], accA[j][3],
                         ahA0, ahA1, ahA2, ahA3, bh0, bh1);
                mma16816(accB[j][0], accB[j][1], accB[j][2], accB[j][3],
                         ahB0, ahB1, ahB2, ahB3, bh0, bh1);
                mma16816(accA[j][0], accA[j][1], accA[j][2], accA[j][3],
                         ahA0, ahA1, ahA2, ahA3, bl0, bl1);
                mma16816(accB[j][0], accB[j][1], accB[j][2], accB[j][3],
                         ahB0, ahB1, ahB2, ahB3, bl0, bl1);
                mma16816(accA[j][0], accA[j][1], accA[j][2], accA[j][3],
                         alA0, alA1, alA2, alA3, bh0, bh1);
                mma16816(accB[j][0], accB[j][1], accB[j][2], accB[j][3],
                         alB0, alB1, alB2, alB3, bh0, bh1);
            }
        }

        // ---- out = relu(acc + b2) . Wd3 + bd3 (both sub-tiles) ----
        {
            float pA0 = 0.f, pA1 = 0.f, pB0 = 0.f, pB1 = 0.f;
#pragma unroll
            for (int j = 0; j < 4; j++) {
                int col0 = cb + j * 8 + 2 * tg;
                float wa = w3s[col0], wb = w3s[col0 + 1];
                pA0 += fmaxf(accA[j][0] + b2s[col0],     0.f) * wa
                     + fmaxf(accA[j][1] + b2s[col0 + 1], 0.f) * wb;
                pA1 += fmaxf(accA[j][2] + b2s[col0],     0.f) * wa
                     + fmaxf(accA[j][3] + b2s[col0 + 1], 0.f) * wb;
                pB0 += fmaxf(accB[j][0] + b2s[col0],     0.f) * wa
                     + fmaxf(accB[j][1] + b2s[col0 + 1], 0.f) * wb;
                pB1 += fmaxf(accB[j][2] + b2s[col0],     0.f) * wa
                     + fmaxf(accB[j][3] + b2s[col0 + 1], 0.f) * wb;
            }
            pA0 += __shfl_xor_sync(0xffffffffu, pA0, 1);
            pA0 += __shfl_xor_sync(0xffffffffu, pA0, 2);
            pA1 += __shfl_xor_sync(0xffffffffu, pA1, 1);
            pA1 += __shfl_xor_sync(0xffffffffu, pA1, 2);
            pB0 += __shfl_xor_sync(0xffffffffu, pB0, 1);
            pB0 += __shfl_xor_sync(0xffffffffu, pB0, 2);
            pB1 += __shfl_xor_sync(0xffffffffu, pB1, 1);
            pB1 += __shfl_xor_sync(0xffffffffu, pB1, 2);
            if (tg == 0) {
                red[(rb + g) * 4 + wc]          = pA0;
                red[(rb + 8 + g) * 4 + wc]      = pA1;
                red[(64 + rb + g) * 4 + wc]     = pB0;
                red[(64 + rb + 8 + g) * 4 + wc] = pB1;
            }
        }
        __syncthreads();

        if (tid < 128) {
            int p = tb + tid;
            if (p < total)
                out[p] = red[tid * 4] + red[tid * 4 + 1]
                       + red[tid * 4 + 2] + red[tid * 4 + 3] + b3;
        }
        __syncthreads();
    }
}

// ============================================================================
// launch — two-stream fork/join with weight pre-split
// ============================================================================
extern "C" void kernel_launch(void* const* d_in, const int* in_sizes, int n_in,
                              void* d_out, int out_size)
{
    const float* x    = (const float*)d_in[0];
    const int*   esrc = (const int*)  d_in[1];
    const int*   edst = (const int*)  d_in[2];
    const int*   ps   = (const int*)  d_in[3];
    const int*   pd   = (const int*)  d_in[4];
    const int*   ns   = (const int*)  d_in[5];
    const int*   nd   = (const int*)  d_in[6];
    const float* Ws1  = (const float*)d_in[7];
    const float* Wn1  = (const float*)d_in[8];
    const float* b1   = (const float*)d_in[9];
    const float* Ws2  = (const float*)d_in[10];
    const float* Wn2  = (const float*)d_in[11];
    const float* b2   = (const float*)d_in[12];
    const float* Wd1  = (const float*)d_in[13];
    const float* bd1  = (const float*)d_in[14];
    const float* Wd2  = (const float*)d_in[15];
    const float* bd2  = (const float*)d_in[16];
    const float* Wd3  = (const float*)d_in[17];
    const float* bd3  = (const float*)d_in[18];
    float* out = (float*)d_out;

    void *aggPtr, *h1Ptr, *h2Ptr, *whPtr, *wlPtr;
    cudaGetSymbolAddress(&aggPtr, g_agg);
    cudaGetSymbolAddress(&h1Ptr,  g_h1);
    cudaGetSymbolAddress(&h2Ptr,  g_h2);
    cudaGetSymbolAddress(&whPtr,  g_Wh);
    cudaGetSymbolAddress(&wlPtr,  g_Wl);
    float* h1 = (float*)h1Ptr;
    float* h2 = (float*)h2Ptr;
    float* agg = (float*)aggPtr;
    const u32* Wh = (const u32*)whPtr;
    const u32* Wl = (const u32*)wlPtr;
    const int WM = 64 * 128;   // entries per matrix

    int nsm = 148;
    cudaDeviceGetAttribute(&nsm, cudaDevAttrMultiProcessorCount, 0);

    int rpb_sage = (((NN + nsm - 1) / nsm) + 127) & ~127;
    int rpb_dec  = (((2 * PP + nsm - 1) / nsm) + 127) & ~127;

    const int SAGE_SMEM = SAGE_U32 * 4;    // ~140 KB
    const int DEC_SMEM  = DEC_U32 * 4;     // ~212.5 KB
    cudaFuncSetAttribute(sage_half_mma<false, false>,
                         cudaFuncAttributeMaxDynamicSharedMemorySize, SAGE_SMEM);
    cudaFuncSetAttribute(sage_half_mma<true, true>,
                         cudaFuncAttributeMaxDynamicSharedMemorySize, SAGE_SMEM);
    cudaFuncSetAttribute(sage_half_mma<true, false>,
                         cudaFuncAttributeMaxDynamicSharedMemorySize, SAGE_SMEM);
    cudaFuncSetAttribute(decoder_kernel,
                         cudaFuncAttributeMaxDynamicSharedMemorySize, DEC_SMEM);

    static cudaStream_t sB = nullptr;
    static cudaEvent_t evSplit = nullptr, evFork = nullptr, evAgg1 = nullptr,
                       evH1 = nullptr, evAgg2 = nullptr;
    if (sB == nullptr) {
        cudaStreamCreateWithFlags(&sB, cudaStreamNonBlocking);
        cudaEventCreateWithFlags(&evSplit, cudaEventDisableTiming);
        cudaEventCreateWithFlags(&evFork, cudaEventDisableTiming);
        cudaEventCreateWithFlags(&evAgg1, cudaEventDisableTiming);
        cudaEventCreateWithFlags(&evH1,   cudaEventDisableTiming);
        cudaEventCreateWithFlags(&evAgg2, cudaEventDisableTiming);
    }

    int ablocks = (NN * 32 + 255) / 256;

    // ---- fork ----
    cudaEventRecord(evFork, 0);
    cudaStreamWaitEvent(sB, evFork, 0);

    // streamB: weight pre-split, then CSR build + aggregate layer 1
    split_weights_kernel<<<(6 * 8192 + 255) / 256, 256, 0, sB>>>(
        Ws1, Wn1, Ws2, Wn2, Wd1, Wd2);
    cudaEventRecord(evSplit, sB);
    count_kernel<<<(EE + 255) / 256, 256, 0, sB>>>(edst);
    scan_kernel<<<1, 1024, 0, sB>>>();
    fill_kernel<<<(EE + 255) / 256, 256, 0, sB>>>(esrc, edst);
    aggregate_kernel<<<ablocks, 256, 0, sB>>>(x);
    cudaEventRecord(evAgg1, sB);

    // streamA: wait for weights, then self half of layer 1
    cudaStreamWaitEvent(0, evSplit, 0);
    sage_half_mma<false, false><<<nsm, 512, SAGE_SMEM>>>(
        x, Wh + 0 * WM, Wl + 0 * WM, b1, h1, rpb_sage);
    cudaStreamWaitEvent(0, evAgg1, 0);
    sage_half_mma<true, true><<<nsm, 512, SAGE_SMEM>>>(
        agg, Wh + 1 * WM, Wl + 1 * WM, b1, h1, rpb_sage);
    cudaEventRecord(evH1, 0);

    // streamB: aggregate layer 2 (concurrent with sage2_self)
    cudaStreamWaitEvent(sB, evH1, 0);
    aggregate_kernel<<<ablocks, 256, 0, sB>>>(h1);
    cudaEventRecord(evAgg2, sB);

    // streamA: self half of layer 2
    sage_half_mma<false, false><<<nsm, 512, SAGE_SMEM>>>(
        h1, Wh + 2 * WM, Wl + 2 * WM, b2, h2, rpb_sage);
    cudaStreamWaitEvent(0, evAgg2, 0);
    sage_half_mma<true, false><<<nsm, 512, SAGE_SMEM>>>(
        agg, Wh + 3 * WM, Wl + 3 * WM, b2, h2, rpb_sage);

    // decoder (128-row double-tile, pre-split weights)
    decoder_kernel<<<nsm, 512, DEC_SMEM>>>(
        h2, ps, pd, ns, nd,
        Wh + 4 * WM, Wl + 4 * WM, Wh + 5 * WM, Wl + 5 * WM,
        bd1, bd2, Wd3, bd3, out, rpb_dec);
}